// round 3
// baseline (speedup 1.0000x reference)
#include <cuda_runtime.h>
#include <cuda_bf16.h>
#include <math_constants.h>

// Problem constants
#define BATCH   32
#define SEQ     257
#define EMBED   1024
#define HEADS   16
#define HEAD_D  64
#define M_ROWS  (BATCH * SEQ)        // 8224
#define ATTN_SCALE 0.125f            // 64^-0.5

// Scratch (device globals; no allocation allowed)
__device__ float g_q[M_ROWS * EMBED];
__device__ float g_k[M_ROWS * EMBED];
__device__ float g_v[M_ROWS * EMBED];
__device__ float g_ctx[M_ROWS * EMBED];

// ---------------------------------------------------------------------------
// GEMM: C[m,n] = (sum_k A[m,k] * W[n,k] + bias[n]) * scale
// A: [M,1024] row-major, W: [1024,1024] row-major (n,k), N=K=1024 fixed.
// Tiles BM=BN=64, BK=16; 256 threads; 4x4 microtile per thread.
// ---------------------------------------------------------------------------
#define BM 64
#define BN 64
#define BK 16

__global__ __launch_bounds__(256, 4)
void gemm_nt_kernel(const float* __restrict__ A,
                    const float* __restrict__ W,
                    const float* __restrict__ bias,
                    float* __restrict__ C,
                    int M, float scale)
{
    __shared__ float As[BK][BM];   // transposed: As[k][m]
    __shared__ float Bs[BK][BN];   // transposed: Bs[k][n]

    const int tid = threadIdx.x;
    const int tr = tid / 16;       // 0..15 -> row group
    const int tc = tid % 16;       // 0..15 -> col group

    const int ldRow  = tid >> 2;          // 0..63
    const int ldCol4 = (tid & 3) << 2;    // 0,4,8,12

    const int m0 = blockIdx.x * BM;
    const int n0 = blockIdx.y * BN;

    const int gm = m0 + ldRow;            // global row for A loads
    const int gn = n0 + ldRow;            // global row for W loads (always < 1024)
    const bool mOk = (gm < M);

    float acc[4][4];
#pragma unroll
    for (int i = 0; i < 4; i++)
#pragma unroll
        for (int j = 0; j < 4; j++) acc[i][j] = 0.f;

    for (int k0 = 0; k0 < EMBED; k0 += BK) {
        // load A tile (transposed into As)
        float4 fa = make_float4(0.f, 0.f, 0.f, 0.f);
        if (mOk)
            fa = *reinterpret_cast<const float4*>(&A[(size_t)gm * EMBED + k0 + ldCol4]);
        As[ldCol4 + 0][ldRow] = fa.x;
        As[ldCol4 + 1][ldRow] = fa.y;
        As[ldCol4 + 2][ldRow] = fa.z;
        As[ldCol4 + 3][ldRow] = fa.w;

        // load W tile (transposed into Bs)
        float4 fb = *reinterpret_cast<const float4*>(&W[(size_t)gn * EMBED + k0 + ldCol4]);
        Bs[ldCol4 + 0][ldRow] = fb.x;
        Bs[ldCol4 + 1][ldRow] = fb.y;
        Bs[ldCol4 + 2][ldRow] = fb.z;
        Bs[ldCol4 + 3][ldRow] = fb.w;

        __syncthreads();

#pragma unroll
        for (int kk = 0; kk < BK; kk++) {
            float4 a4 = *reinterpret_cast<const float4*>(&As[kk][tr * 4]);
            float4 b4 = *reinterpret_cast<const float4*>(&Bs[kk][tc * 4]);
            float ar[4] = {a4.x, a4.y, a4.z, a4.w};
            float br[4] = {b4.x, b4.y, b4.z, b4.w};
#pragma unroll
            for (int i = 0; i < 4; i++)
#pragma unroll
                for (int j = 0; j < 4; j++)
                    acc[i][j] = fmaf(ar[i], br[j], acc[i][j]);
        }
        __syncthreads();
    }

    // epilogue: bias + scale, guarded store
#pragma unroll
    for (int j = 0; j < 4; j++) {
        const int n = n0 + tc * 4 + j;
        const float bn = bias[n];
#pragma unroll
        for (int i = 0; i < 4; i++) {
            const int m = m0 + tr * 4 + i;
            if (m < M)
                C[(size_t)m * EMBED + n] = (acc[i][j] + bn) * scale;
        }
    }
}

// ---------------------------------------------------------------------------
// Attention: one block per (batch, head). K/V staged in smem (ld=65, padded,
// conflict-free). 8 warps; each warp owns query rows i = w, w+8, ...
// ---------------------------------------------------------------------------
#define LDKV 65
#define NWARP 8

__global__ __launch_bounds__(256, 1)
void attn_kernel()
{
    extern __shared__ float sm[];
    float* Ks = sm;                       // SEQ * LDKV
    float* Vs = Ks + SEQ * LDKV;          // SEQ * LDKV
    float* Ps = Vs + SEQ * LDKV;          // NWARP * SEQ
    float* Qs = Ps + NWARP * SEQ;         // NWARP * 64

    const int tid  = threadIdx.x;
    const int w    = tid >> 5;
    const int lane = tid & 31;
    const int b = blockIdx.x >> 4;
    const int h = blockIdx.x & 15;

    const size_t base = (size_t)b * SEQ * EMBED + h * HEAD_D;

    // stage K and V tiles
    for (int idx = tid; idx < SEQ * 16; idx += 256) {
        const int j = idx >> 4;
        const int c = (idx & 15) << 2;
        float4 fk = *reinterpret_cast<const float4*>(&g_k[base + (size_t)j * EMBED + c]);
        float4 fv = *reinterpret_cast<const float4*>(&g_v[base + (size_t)j * EMBED + c]);
        float* dk = &Ks[j * LDKV + c];
        float* dv = &Vs[j * LDKV + c];
        dk[0] = fk.x; dk[1] = fk.y; dk[2] = fk.z; dk[3] = fk.w;
        dv[0] = fv.x; dv[1] = fv.y; dv[2] = fv.z; dv[3] = fv.w;
    }
    __syncthreads();

    for (int i = w; i < SEQ; i += NWARP) {
        // load Q row (already scaled by ATTN_SCALE in projection)
        const float* qrow = &g_q[base + (size_t)i * EMBED];
        Qs[w * 64 + lane]      = qrow[lane];
        Qs[w * 64 + lane + 32] = qrow[lane + 32];
        __syncwarp();

        // scores: lane handles j = lane + 32*r (r<8); j=256 computed uniformly
        float s[8];
#pragma unroll
        for (int r = 0; r < 8; r++) s[r] = 0.f;
        float s8 = 0.f;  // j = 256, identical on all lanes (broadcast reads)

#pragma unroll 4
        for (int d = 0; d < HEAD_D; d++) {
            const float qd = Qs[w * 64 + d];
#pragma unroll
            for (int r = 0; r < 8; r++)
                s[r] = fmaf(qd, Ks[(lane + (r << 5)) * LDKV + d], s[r]);
            s8 = fmaf(qd, Ks[256 * LDKV + d], s8);
        }

        // softmax (warp-level)
        float mx = s[0];
#pragma unroll
        for (int r = 1; r < 8; r++) mx = fmaxf(mx, s[r]);
#pragma unroll
        for (int off = 16; off > 0; off >>= 1)
            mx = fmaxf(mx, __shfl_xor_sync(0xffffffffu, mx, off));
        mx = fmaxf(mx, s8);

        float p[8], lsum = 0.f;
#pragma unroll
        for (int r = 0; r < 8; r++) { p[r] = __expf(s[r] - mx); lsum += p[r]; }
#pragma unroll
        for (int off = 16; off > 0; off >>= 1)
            lsum += __shfl_xor_sync(0xffffffffu, lsum, off);
        const float p8 = __expf(s8 - mx);
        const float inv = 1.f / (lsum + p8);

#pragma unroll
        for (int r = 0; r < 8; r++)
            Ps[w * SEQ + lane + (r << 5)] = p[r] * inv;
        if (lane == 0) Ps[w * SEQ + 256] = p8 * inv;
        __syncwarp();

        // ctx[i,d] = sum_j P[j] * V[j,d]; lane owns d=lane and d=lane+32
        float acc0 = 0.f, acc1 = 0.f;
#pragma unroll 4
        for (int j = 0; j < SEQ; j++) {
            const float pj = Ps[w * SEQ + j];
            acc0 = fmaf(pj, Vs[j * LDKV + lane],      acc0);
            acc1 = fmaf(pj, Vs[j * LDKV + lane + 32], acc1);
        }
        float* crow = &g_ctx[base + (size_t)i * EMBED];
        crow[lane]      = acc0;
        crow[lane + 32] = acc1;
        __syncwarp();
    }
}

// ---------------------------------------------------------------------------
extern "C" void kernel_launch(void* const* d_in, const int* in_sizes, int n_in,
                              void* d_out, int out_size)
{
    const float* X  = (const float*)d_in[0];
    const float* Wq = (const float*)d_in[1];
    const float* bq = (const float*)d_in[2];
    const float* Wk = (const float*)d_in[3];
    const float* bk = (const float*)d_in[4];
    const float* Wv = (const float*)d_in[5];
    const float* bv = (const float*)d_in[6];
    const float* Wo = (const float*)d_in[7];
    const float* bo = (const float*)d_in[8];
    float* out = (float*)d_out;

    float *q, *k, *v, *ctx;
    cudaGetSymbolAddress((void**)&q,   g_q);
    cudaGetSymbolAddress((void**)&k,   g_k);
    cudaGetSymbolAddress((void**)&v,   g_v);
    cudaGetSymbolAddress((void**)&ctx, g_ctx);

    const dim3 gGrid((M_ROWS + BM - 1) / BM, EMBED / BN);
    const dim3 gBlk(256);

    // Q/K/V projections (Q fused with attention scale)
    gemm_nt_kernel<<<gGrid, gBlk>>>(X, Wq, bq, q, M_ROWS, ATTN_SCALE);
    gemm_nt_kernel<<<gGrid, gBlk>>>(X, Wk, bk, k, M_ROWS, 1.0f);
    gemm_nt_kernel<<<gGrid, gBlk>>>(X, Wv, bv, v, M_ROWS, 1.0f);

    // attention
    const int smemBytes = (2 * SEQ * LDKV + NWARP * SEQ + NWARP * 64) * (int)sizeof(float);
    cudaFuncSetAttribute(attn_kernel, cudaFuncAttributeMaxDynamicSharedMemorySize, smemBytes);
    attn_kernel<<<BATCH * HEADS, 256, smemBytes>>>();

    // output projection
    gemm_nt_kernel<<<gGrid, gBlk>>>(ctx, Wo, bo, out, M_ROWS, 1.0f);
}

// round 6
// speedup vs baseline: 2.7113x; 2.7113x over previous
#include <cstdint>
#include <cstdio>
#include <cuda_runtime.h>
#include <cuda_bf16.h>
#include <math_constants.h>

// Problem constants
#define BATCH   32
#define SEQ     257
#define EMBED   1024
#define HEADS   16
#define HEAD_D  64
#define M_ROWS  (BATCH * SEQ)        // 8224
#define ATTN_SCALE 0.125f            // 64^-0.5

// Scratch (device globals; no allocation allowed)
__device__ float g_q[M_ROWS * EMBED];
__device__ float g_k[M_ROWS * EMBED];
__device__ float g_v[M_ROWS * EMBED];
__device__ float g_ctx[M_ROWS * EMBED];

// ===========================================================================
// TF32 tensor-core GEMM:  C[m,n] = (sum_k A[m,k]*W[n,k] + bias[n]) * scale
// A:[M,1024] row-major, W:[1024,1024] row-major as [n,k].
// CTA tile 128x128x16, 256 threads (8 warps), warp tile 64x32,
// mma.sync.aligned.m16n8k8.row.col.f32.tf32.tf32.f32
// ===========================================================================
#define GBM 128
#define GBN 128
#define GBK 16
#define GS  24          // padded smem row stride (floats) -> conflict-free LDS.64

__device__ __forceinline__ uint32_t f2tf32(float f) {
    uint32_t u;
    asm("cvt.rna.tf32.f32 %0, %1;" : "=r"(u) : "f"(f));
    return u;
}

__device__ __forceinline__ void mma_tf32(float& c0, float& c1, float& c2, float& c3,
                                         uint32_t a0, uint32_t a1, uint32_t a2, uint32_t a3,
                                         uint32_t b0, uint32_t b1) {
    asm volatile("mma.sync.aligned.m16n8k8.row.col.f32.tf32.tf32.f32 "
                 "{%0,%1,%2,%3}, {%4,%5,%6,%7}, {%8,%9}, {%0,%1,%2,%3};"
                 : "+f"(c0), "+f"(c1), "+f"(c2), "+f"(c3)
                 : "r"(a0), "r"(a1), "r"(a2), "r"(a3), "r"(b0), "r"(b1));
}

// column permutation within a BK=16 tile: k8 group kept, within group
// col c -> p = ((c&3)<<1) | (c>>2)  so (t, t+4) land adjacent -> LDS.64 frags
__device__ __forceinline__ int permcol(int c) {
    int k8 = c >> 3;
    int cc = c & 7;
    return (k8 << 3) + ((cc & 3) << 1) + (cc >> 2);
}

__global__ __launch_bounds__(256, 2)
void gemm_tf32_kernel(const float* __restrict__ A,
                      const float* __restrict__ W,
                      const float* __restrict__ bias,
                      float* __restrict__ C,
                      int M, float scale)
{
    __shared__ uint32_t As[GBM * GS];
    __shared__ uint32_t Bs[GBN * GS];

    const int tid   = threadIdx.x;
    const int warp  = tid >> 5;
    const int lane  = tid & 31;
    const int warpM = warp >> 2;     // 0..1
    const int warpN = warp & 3;      // 0..3
    const int g     = lane >> 2;     // groupID
    const int t     = lane & 3;      // threadID in group

    const int m0 = blockIdx.x * GBM;
    const int n0 = blockIdx.y * GBN;

    // global-load mapping: 512 float4 per tile / 256 threads = 2 each
    const int r0 = tid >> 2;                 // rows tid/4 and tid/4+64
    const int c4 = (tid & 3) << 2;           // col start (0,4,8,12)
    const bool aOk0 = (m0 + r0)      < M;
    const bool aOk1 = (m0 + r0 + 64) < M;

    float cacc[4][4][4];
#pragma unroll
    for (int i = 0; i < 4; i++)
#pragma unroll
        for (int j = 0; j < 4; j++)
#pragma unroll
            for (int e = 0; e < 4; e++) cacc[i][j][e] = 0.f;

    float4 pa0, pa1, pb0, pb1;
    const float4 z4 = make_float4(0.f, 0.f, 0.f, 0.f);

    // prologue: load k0 = 0
    {
        const int k0 = 0;
        pa0 = aOk0 ? *(const float4*)&A[(size_t)(m0 + r0)      * EMBED + k0 + c4] : z4;
        pa1 = aOk1 ? *(const float4*)&A[(size_t)(m0 + r0 + 64) * EMBED + k0 + c4] : z4;
        pb0 = *(const float4*)&W[(size_t)(n0 + r0)      * EMBED + k0 + c4];
        pb1 = *(const float4*)&W[(size_t)(n0 + r0 + 64) * EMBED + k0 + c4];
    }

    for (int k0 = 0; k0 < EMBED; k0 += GBK) {
        __syncthreads();
        // store staged tiles (tf32-converted, permuted columns)
        {
            const float va0[4] = {pa0.x, pa0.y, pa0.z, pa0.w};
            const float va1[4] = {pa1.x, pa1.y, pa1.z, pa1.w};
            const float vb0[4] = {pb0.x, pb0.y, pb0.z, pb0.w};
            const float vb1[4] = {pb1.x, pb1.y, pb1.z, pb1.w};
#pragma unroll
            for (int e = 0; e < 4; e++) {
                const int p = permcol(c4 + e);
                As[r0        * GS + p] = f2tf32(va0[e]);
                As[(r0 + 64) * GS + p] = f2tf32(va1[e]);
                Bs[r0        * GS + p] = f2tf32(vb0[e]);
                Bs[(r0 + 64) * GS + p] = f2tf32(vb1[e]);
            }
        }
        __syncthreads();

        // prefetch next tile
        if (k0 + GBK < EMBED) {
            const int kn = k0 + GBK;
            pa0 = aOk0 ? *(const float4*)&A[(size_t)(m0 + r0)      * EMBED + kn + c4] : z4;
            pa1 = aOk1 ? *(const float4*)&A[(size_t)(m0 + r0 + 64) * EMBED + kn + c4] : z4;
            pb0 = *(const float4*)&W[(size_t)(n0 + r0)      * EMBED + kn + c4];
            pb1 = *(const float4*)&W[(size_t)(n0 + r0 + 64) * EMBED + kn + c4];
        }

        // compute 2 k8 steps
#pragma unroll
        for (int s = 0; s < 2; s++) {
            uint32_t af[4][4];   // [mtile][a0..a3]
#pragma unroll
            for (int mt = 0; mt < 4; mt++) {
                const int row0 = warpM * 64 + mt * 16;
                uint2 lo = *(const uint2*)&As[(row0 + g)     * GS + s * 8 + 2 * t];
                uint2 hi = *(const uint2*)&As[(row0 + 8 + g) * GS + s * 8 + 2 * t];
                af[mt][0] = lo.x;   // (g,   t)
                af[mt][1] = hi.x;   // (g+8, t)
                af[mt][2] = lo.y;   // (g,   t+4)
                af[mt][3] = hi.y;   // (g+8, t+4)
            }
#pragma unroll
            for (int nt = 0; nt < 4; nt++) {
                const int nn0 = warpN * 32 + nt * 8;
                uint2 bb = *(const uint2*)&Bs[(nn0 + g) * GS + s * 8 + 2 * t];
#pragma unroll
                for (int mt = 0; mt < 4; mt++) {
                    mma_tf32(cacc[mt][nt][0], cacc[mt][nt][1], cacc[mt][nt][2], cacc[mt][nt][3],
                             af[mt][0], af[mt][1], af[mt][2], af[mt][3], bb.x, bb.y);
                }
            }
        }
    }

    // epilogue: bias + scale
#pragma unroll
    for (int nt = 0; nt < 4; nt++) {
        const int col = n0 + warpN * 32 + nt * 8 + 2 * t;
        const float bn0 = bias[col];
        const float bn1 = bias[col + 1];
#pragma unroll
        for (int mt = 0; mt < 4; mt++) {
            const int row  = m0 + warpM * 64 + mt * 16 + g;
            const int row2 = row + 8;
            if (row < M) {
                float2 o = make_float2((cacc[mt][nt][0] + bn0) * scale,
                                       (cacc[mt][nt][1] + bn1) * scale);
                *(float2*)&C[(size_t)row * EMBED + col] = o;
            }
            if (row2 < M) {
                float2 o = make_float2((cacc[mt][nt][2] + bn0) * scale,
                                       (cacc[mt][nt][3] + bn1) * scale);
                *(float2*)&C[(size_t)row2 * EMBED + col] = o;
            }
        }
    }
}

// ===========================================================================
// Attention: one CTA per (b,h). 512 threads = 16 warps; each warp processes
// G=4 query rows per pass (K/V smem traffic amortized 4x). K/V in smem,
// LDK=66 (float2 conflict-free). Probs staged per-warp in smem.
// ===========================================================================
#define AW   16
#define ATHR 512
#define LDK  66
#define PLD  260
#define G    4

__global__ __launch_bounds__(ATHR, 1)
void attn_kernel()
{
    extern __shared__ float sm[];
    float* Ks = sm;                         // SEQ * LDK
    float* Vs = Ks + SEQ * LDK;             // SEQ * LDK
    float* Qs = Vs + SEQ * LDK;             // AW * G * 64
    float* Ps = Qs + AW * G * 64;           // AW * G * PLD

    const int tid  = threadIdx.x;
    const int w    = tid >> 5;
    const int lane = tid & 31;
    const int b = blockIdx.x >> 4;
    const int h = blockIdx.x & 15;

    const size_t base = (size_t)b * SEQ * EMBED + h * HEAD_D;

    // stage K and V
    for (int idx = tid; idx < SEQ * 16; idx += ATHR) {
        const int j = idx >> 4;
        const int c = (idx & 15) << 2;
        float4 fk = *(const float4*)&g_k[base + (size_t)j * EMBED + c];
        float4 fv = *(const float4*)&g_v[base + (size_t)j * EMBED + c];
        float* dk = &Ks[j * LDK + c];
        float* dv = &Vs[j * LDK + c];
        dk[0] = fk.x; dk[1] = fk.y; dk[2] = fk.z; dk[3] = fk.w;
        dv[0] = fv.x; dv[1] = fv.y; dv[2] = fv.z; dv[3] = fv.w;
    }
    __syncthreads();

    const int dd = lane * 2;   // this lane's 2 head dims for PV

    for (int i0 = w * G; i0 < SEQ; i0 += AW * G) {
        // load Q rows (clamped; invalid rows discarded at store)
#pragma unroll
        for (int rr = 0; rr < G; rr++) {
            int r = i0 + rr;
            if (r >= SEQ) r = SEQ - 1;
            Qs[(w * G + rr) * 64 + lane]      = g_q[base + (size_t)r * EMBED + lane];
            Qs[(w * G + rr) * 64 + lane + 32] = g_q[base + (size_t)r * EMBED + lane + 32];
        }
        __syncwarp();

        // scores
        float s[G][8];
        float s8[G];
#pragma unroll
        for (int rr = 0; rr < G; rr++) {
            s8[rr] = 0.f;
#pragma unroll
            for (int r = 0; r < 8; r++) s[rr][r] = 0.f;
        }

#pragma unroll 2
        for (int d2 = 0; d2 < 32; d2++) {
            const int d = d2 << 1;
            float2 q2[G];
#pragma unroll
            for (int rr = 0; rr < G; rr++)
                q2[rr] = *(const float2*)&Qs[(w * G + rr) * 64 + d];
#pragma unroll
            for (int r = 0; r < 8; r++) {
                float2 kv = *(const float2*)&Ks[(lane + (r << 5)) * LDK + d];
#pragma unroll
                for (int rr = 0; rr < G; rr++)
                    s[rr][r] = fmaf(q2[rr].x, kv.x, fmaf(q2[rr].y, kv.y, s[rr][r]));
            }
            float2 k8 = *(const float2*)&Ks[256 * LDK + d];
#pragma unroll
            for (int rr = 0; rr < G; rr++)
                s8[rr] = fmaf(q2[rr].x, k8.x, fmaf(q2[rr].y, k8.y, s8[rr]));
        }

        // softmax + write probs
#pragma unroll
        for (int rr = 0; rr < G; rr++) {
            float mx = s[rr][0];
#pragma unroll
            for (int r = 1; r < 8; r++) mx = fmaxf(mx, s[rr][r]);
#pragma unroll
            for (int off = 16; off > 0; off >>= 1)
                mx = fmaxf(mx, __shfl_xor_sync(0xffffffffu, mx, off));
            mx = fmaxf(mx, s8[rr]);

            float p[8], lsum = 0.f;
#pragma unroll
            for (int r = 0; r < 8; r++) { p[r] = __expf(s[rr][r] - mx); lsum += p[r]; }
#pragma unroll
            for (int off = 16; off > 0; off >>= 1)
                lsum += __shfl_xor_sync(0xffffffffu, lsum, off);
            const float p8  = __expf(s8[rr] - mx);
            const float inv = 1.f / (lsum + p8);

#pragma unroll
            for (int r = 0; r < 8; r++)
                Ps[(w * G + rr) * PLD + lane + (r << 5)] = p[r] * inv;
            if (lane == 0) Ps[(w * G + rr) * PLD + 256] = p8 * inv;
        }
        __syncwarp();

        // PV: ctx[i, dd..dd+1]
        float2 acc[G];
#pragma unroll
        for (int rr = 0; rr < G; rr++) acc[rr] = make_float2(0.f, 0.f);

        for (int j = 0; j < 256; j += 4) {
            float4 pr[G];
#pragma unroll
            for (int rr = 0; rr < G; rr++)
                pr[rr] = *(const float4*)&Ps[(w * G + rr) * PLD + j];
#pragma unroll
            for (int jj = 0; jj < 4; jj++) {
                float2 v = *(const float2*)&Vs[(j + jj) * LDK + dd];
#pragma unroll
                for (int rr = 0; rr < G; rr++) {
                    const float pv = (jj == 0) ? pr[rr].x : (jj == 1) ? pr[rr].y
                                   : (jj == 2) ? pr[rr].z : pr[rr].w;
                    acc[rr].x = fmaf(pv, v.x, acc[rr].x);
                    acc[rr].y = fmaf(pv, v.y, acc[rr].y);
                }
            }
        }
        // tail j = 256
        {
            float2 v = *(const float2*)&Vs[256 * LDK + dd];
#pragma unroll
            for (int rr = 0; rr < G; rr++) {
                const float pv = Ps[(w * G + rr) * PLD + 256];
                acc[rr].x = fmaf(pv, v.x, acc[rr].x);
                acc[rr].y = fmaf(pv, v.y, acc[rr].y);
            }
        }

#pragma unroll
        for (int rr = 0; rr < G; rr++) {
            const int r = i0 + rr;
            if (r < SEQ)
                *(float2*)&g_ctx[base + (size_t)r * EMBED + dd] = acc[rr];
        }
        __syncwarp();
    }
}

// ===========================================================================
extern "C" void kernel_launch(void* const* d_in, const int* in_sizes, int n_in,
                              void* d_out, int out_size)
{
    const float* X  = (const float*)d_in[0];
    const float* Wq = (const float*)d_in[1];
    const float* bq = (const float*)d_in[2];
    const float* Wk = (const float*)d_in[3];
    const float* bk = (const float*)d_in[4];
    const float* Wv = (const float*)d_in[5];
    const float* bv = (const float*)d_in[6];
    const float* Wo = (const float*)d_in[7];
    const float* bo = (const float*)d_in[8];
    float* out = (float*)d_out;

    float *q, *k, *v, *ctx;
    cudaGetSymbolAddress((void**)&q,   g_q);
    cudaGetSymbolAddress((void**)&k,   g_k);
    cudaGetSymbolAddress((void**)&v,   g_v);
    cudaGetSymbolAddress((void**)&ctx, g_ctx);

    const dim3 gGrid((M_ROWS + GBM - 1) / GBM, EMBED / GBN);   // 65 x 8
    const dim3 gBlk(256);

    // Q/K/V projections (Q fused with attention scale)
    gemm_tf32_kernel<<<gGrid, gBlk>>>(X, Wq, bq, q, M_ROWS, ATTN_SCALE);
    gemm_tf32_kernel<<<gGrid, gBlk>>>(X, Wk, bk, k, M_ROWS, 1.0f);
    gemm_tf32_kernel<<<gGrid, gBlk>>>(X, Wv, bv, v, M_ROWS, 1.0f);

    // attention
    const int smemBytes = (2 * SEQ * LDK + AW * G * 64 + AW * G * PLD) * (int)sizeof(float);
    cudaFuncSetAttribute(attn_kernel, cudaFuncAttributeMaxDynamicSharedMemorySize, smemBytes);
    attn_kernel<<<BATCH * HEADS, ATHR, smemBytes>>>();

    // output projection
    gemm_tf32_kernel<<<gGrid, gBlk>>>(ctx, Wo, bo, out, M_ROWS, 1.0f);
}

// round 7
// speedup vs baseline: 3.0455x; 1.1233x over previous
#include <cstdint>
#include <cstdio>
#include <cuda_runtime.h>
#include <cuda_bf16.h>
#include <math_constants.h>

// Problem constants
#define BATCH   32
#define SEQ     257
#define EMBED   1024
#define HEADS   16
#define HEAD_D  64
#define M_ROWS  (BATCH * SEQ)        // 8224
#define ATTN_SCALE 0.125f            // 64^-0.5

// Scratch (device globals; no allocation allowed)
__device__ float g_q[M_ROWS * EMBED];
__device__ float g_k[M_ROWS * EMBED];
__device__ float g_v[M_ROWS * EMBED];
__device__ float g_ctx[M_ROWS * EMBED];

// ===========================================================================
// TF32 tensor-core GEMM core:  C[m,n] = (sum_k A[m,k]*W[n,k] + bias[n])*scale
// CTA tile 128x128x16, 256 thr (8 warps), warp tile 64x32, m16n8k8 tf32 mma.
// Double-buffered smem: ONE __syncthreads per k-iteration; global prefetch
// issued before compute to overlap DRAM/L2 latency with MMA work.
// ===========================================================================
#define GBM 128
#define GBN 128
#define GBK 16
#define GS  24          // padded smem row stride (u32) -> conflict-free LDS.64

__device__ __forceinline__ uint32_t f2tf32(float f) {
    uint32_t u;
    asm("cvt.rna.tf32.f32 %0, %1;" : "=r"(u) : "f"(f));
    return u;
}

__device__ __forceinline__ void mma_tf32(float& c0, float& c1, float& c2, float& c3,
                                         uint32_t a0, uint32_t a1, uint32_t a2, uint32_t a3,
                                         uint32_t b0, uint32_t b1) {
    asm volatile("mma.sync.aligned.m16n8k8.row.col.f32.tf32.tf32.f32 "
                 "{%0,%1,%2,%3}, {%4,%5,%6,%7}, {%8,%9}, {%0,%1,%2,%3};"
                 : "+f"(c0), "+f"(c1), "+f"(c2), "+f"(c3)
                 : "r"(a0), "r"(a1), "r"(a2), "r"(a3), "r"(b0), "r"(b1));
}

// col c -> p so that (t, t+4) land adjacent -> LDS.64 fragment loads
__device__ __forceinline__ int permcol(int c) {
    int k8 = c >> 3;
    int cc = c & 7;
    return (k8 << 3) + ((cc & 3) << 1) + (cc >> 2);
}

struct GemmSmem {
    uint32_t As[2][GBM * GS];
    uint32_t Bs[2][GBN * GS];
};

__device__ __forceinline__
void gemm_core(const float* __restrict__ A,
               const float* __restrict__ W,
               const float* __restrict__ bias,
               float* __restrict__ C,
               int M, float scale, GemmSmem& sh)
{
    const int tid   = threadIdx.x;
    const int warp  = tid >> 5;
    const int lane  = tid & 31;
    const int warpM = warp >> 2;     // 0..1
    const int warpN = warp & 3;      // 0..3
    const int g     = lane >> 2;
    const int t     = lane & 3;

    const int m0 = blockIdx.x * GBM;
    const int n0 = blockIdx.y * GBN;

    const int r0 = tid >> 2;                 // rows r0 and r0+64
    const int c4 = (tid & 3) << 2;           // col start (0,4,8,12)
    const bool aOk0 = (m0 + r0)      < M;
    const bool aOk1 = (m0 + r0 + 64) < M;

    // permuted store offsets (precomputed)
    int pc[4];
#pragma unroll
    for (int e = 0; e < 4; e++) pc[e] = permcol(c4 + e);

    float cacc[4][4][4];
#pragma unroll
    for (int i = 0; i < 4; i++)
#pragma unroll
        for (int j = 0; j < 4; j++)
#pragma unroll
            for (int e = 0; e < 4; e++) cacc[i][j][e] = 0.f;

    const float4 z4 = make_float4(0.f, 0.f, 0.f, 0.f);
    const float* pA0 = &A[(size_t)(m0 + r0)      * EMBED + c4];
    const float* pA1 = &A[(size_t)(m0 + r0 + 64) * EMBED + c4];
    const float* pB0 = &W[(size_t)(n0 + r0)      * EMBED + c4];
    const float* pB1 = &W[(size_t)(n0 + r0 + 64) * EMBED + c4];

    // prologue: tile 0 -> buffer 0
    {
        float4 a0 = aOk0 ? *(const float4*)pA0 : z4;
        float4 a1 = aOk1 ? *(const float4*)pA1 : z4;
        float4 b0 = *(const float4*)pB0;
        float4 b1 = *(const float4*)pB1;
        const float va0[4] = {a0.x, a0.y, a0.z, a0.w};
        const float va1[4] = {a1.x, a1.y, a1.z, a1.w};
        const float vb0[4] = {b0.x, b0.y, b0.z, b0.w};
        const float vb1[4] = {b1.x, b1.y, b1.z, b1.w};
#pragma unroll
        for (int e = 0; e < 4; e++) {
            sh.As[0][r0        * GS + pc[e]] = f2tf32(va0[e]);
            sh.As[0][(r0 + 64) * GS + pc[e]] = f2tf32(va1[e]);
            sh.Bs[0][r0        * GS + pc[e]] = f2tf32(vb0[e]);
            sh.Bs[0][(r0 + 64) * GS + pc[e]] = f2tf32(vb1[e]);
        }
    }
    __syncthreads();

    int p = 0;
    for (int k0 = 0; k0 < EMBED; k0 += GBK) {
        const bool more = (k0 + GBK < EMBED);
        float4 a0, a1, b0, b1;
        if (more) {
            const int kn = k0 + GBK;
            a0 = aOk0 ? *(const float4*)(pA0 + kn) : z4;
            a1 = aOk1 ? *(const float4*)(pA1 + kn) : z4;
            b0 = *(const float4*)(pB0 + kn);
            b1 = *(const float4*)(pB1 + kn);
        }

        // compute from buffer p (2 k8 steps)
        const uint32_t* Asp = sh.As[p];
        const uint32_t* Bsp = sh.Bs[p];
#pragma unroll
        for (int s = 0; s < 2; s++) {
            uint32_t af[4][4];
#pragma unroll
            for (int mt = 0; mt < 4; mt++) {
                const int row0 = warpM * 64 + mt * 16;
                uint2 lo = *(const uint2*)&Asp[(row0 + g)     * GS + s * 8 + 2 * t];
                uint2 hi = *(const uint2*)&Asp[(row0 + 8 + g) * GS + s * 8 + 2 * t];
                af[mt][0] = lo.x; af[mt][1] = hi.x; af[mt][2] = lo.y; af[mt][3] = hi.y;
            }
#pragma unroll
            for (int nt = 0; nt < 4; nt++) {
                const int nn0 = warpN * 32 + nt * 8;
                uint2 bb = *(const uint2*)&Bsp[(nn0 + g) * GS + s * 8 + 2 * t];
#pragma unroll
                for (int mt = 0; mt < 4; mt++) {
                    mma_tf32(cacc[mt][nt][0], cacc[mt][nt][1], cacc[mt][nt][2], cacc[mt][nt][3],
                             af[mt][0], af[mt][1], af[mt][2], af[mt][3], bb.x, bb.y);
                }
            }
        }

        if (more) {
            // store prefetched tile into the other buffer; safe: last read of
            // buffer p^1 was before the previous iteration's barrier.
            uint32_t* Asn = sh.As[p ^ 1];
            uint32_t* Bsn = sh.Bs[p ^ 1];
            const float va0[4] = {a0.x, a0.y, a0.z, a0.w};
            const float va1[4] = {a1.x, a1.y, a1.z, a1.w};
            const float vb0[4] = {b0.x, b0.y, b0.z, b0.w};
            const float vb1[4] = {b1.x, b1.y, b1.z, b1.w};
#pragma unroll
            for (int e = 0; e < 4; e++) {
                Asn[r0        * GS + pc[e]] = f2tf32(va0[e]);
                Asn[(r0 + 64) * GS + pc[e]] = f2tf32(va1[e]);
                Bsn[r0        * GS + pc[e]] = f2tf32(vb0[e]);
                Bsn[(r0 + 64) * GS + pc[e]] = f2tf32(vb1[e]);
            }
            __syncthreads();
            p ^= 1;
        }
    }

    // epilogue: bias + scale
#pragma unroll
    for (int nt = 0; nt < 4; nt++) {
        const int col = n0 + warpN * 32 + nt * 8 + 2 * t;
        const float bn0 = bias[col];
        const float bn1 = bias[col + 1];
#pragma unroll
        for (int mt = 0; mt < 4; mt++) {
            const int row  = m0 + warpM * 64 + mt * 16 + g;
            const int row2 = row + 8;
            if (row < M) {
                float2 o = make_float2((cacc[mt][nt][0] + bn0) * scale,
                                       (cacc[mt][nt][1] + bn1) * scale);
                *(float2*)&C[(size_t)row * EMBED + col] = o;
            }
            if (row2 < M) {
                float2 o = make_float2((cacc[mt][nt][2] + bn0) * scale,
                                       (cacc[mt][nt][3] + bn1) * scale);
                *(float2*)&C[(size_t)row2 * EMBED + col] = o;
            }
        }
    }
}

// Fused QKV: blockIdx.z selects {Wq,Wk,Wv}. One launch = 1560 CTAs -> small tail.
__global__ __launch_bounds__(256, 2)
void gemm_qkv_kernel(const float* __restrict__ X,
                     const float* __restrict__ Wq, const float* __restrict__ bq,
                     const float* __restrict__ Wk, const float* __restrict__ bk,
                     const float* __restrict__ Wv, const float* __restrict__ bv,
                     float* __restrict__ q, float* __restrict__ k, float* __restrict__ v)
{
    __shared__ GemmSmem sh;
    const int z = blockIdx.z;
    const float* W    = (z == 0) ? Wq : (z == 1) ? Wk : Wv;
    const float* bias = (z == 0) ? bq : (z == 1) ? bk : bv;
    float*       C    = (z == 0) ? q  : (z == 1) ? k  : v;
    const float scale = (z == 0) ? ATTN_SCALE : 1.0f;
    gemm_core(X, W, bias, C, M_ROWS, scale, sh);
}

__global__ __launch_bounds__(256, 2)
void gemm_single_kernel(const float* __restrict__ A, const float* __restrict__ W,
                        const float* __restrict__ bias, float* __restrict__ C,
                        int M, float scale)
{
    __shared__ GemmSmem sh;
    gemm_core(A, W, bias, C, M, scale, sh);
}

// ===========================================================================
// Attention: one CTA per (b,h). 512 threads = 16 warps; each warp processes
// G=4 query rows per pass. K/V in smem (LDK=66 conflict-free float2).
// ===========================================================================
#define AW   16
#define ATHR 512
#define LDK  66
#define PLD  260
#define G    4

__global__ __launch_bounds__(ATHR, 1)
void attn_kernel()
{
    extern __shared__ float sm[];
    float* Ks = sm;                         // SEQ * LDK
    float* Vs = Ks + SEQ * LDK;             // SEQ * LDK
    float* Qs = Vs + SEQ * LDK;             // AW * G * 64
    float* Ps = Qs + AW * G * 64;           // AW * G * PLD

    const int tid  = threadIdx.x;
    const int w    = tid >> 5;
    const int lane = tid & 31;
    const int b = blockIdx.x >> 4;
    const int h = blockIdx.x & 15;

    const size_t base = (size_t)b * SEQ * EMBED + h * HEAD_D;

    // stage K and V
    for (int idx = tid; idx < SEQ * 16; idx += ATHR) {
        const int j = idx >> 4;
        const int c = (idx & 15) << 2;
        float4 fk = *(const float4*)&g_k[base + (size_t)j * EMBED + c];
        float4 fv = *(const float4*)&g_v[base + (size_t)j * EMBED + c];
        float* dk = &Ks[j * LDK + c];
        float* dv = &Vs[j * LDK + c];
        dk[0] = fk.x; dk[1] = fk.y; dk[2] = fk.z; dk[3] = fk.w;
        dv[0] = fv.x; dv[1] = fv.y; dv[2] = fv.z; dv[3] = fv.w;
    }
    __syncthreads();

    const int dd = lane * 2;

    for (int i0 = w * G; i0 < SEQ; i0 += AW * G) {
#pragma unroll
        for (int rr = 0; rr < G; rr++) {
            int r = i0 + rr;
            if (r >= SEQ) r = SEQ - 1;
            Qs[(w * G + rr) * 64 + lane]      = g_q[base + (size_t)r * EMBED + lane];
            Qs[(w * G + rr) * 64 + lane + 32] = g_q[base + (size_t)r * EMBED + lane + 32];
        }
        __syncwarp();

        float s[G][8];
        float s8[G];
#pragma unroll
        for (int rr = 0; rr < G; rr++) {
            s8[rr] = 0.f;
#pragma unroll
            for (int r = 0; r < 8; r++) s[rr][r] = 0.f;
        }

#pragma unroll 2
        for (int d2 = 0; d2 < 32; d2++) {
            const int d = d2 << 1;
            float2 q2[G];
#pragma unroll
            for (int rr = 0; rr < G; rr++)
                q2[rr] = *(const float2*)&Qs[(w * G + rr) * 64 + d];
#pragma unroll
            for (int r = 0; r < 8; r++) {
                float2 kv = *(const float2*)&Ks[(lane + (r << 5)) * LDK + d];
#pragma unroll
                for (int rr = 0; rr < G; rr++)
                    s[rr][r] = fmaf(q2[rr].x, kv.x, fmaf(q2[rr].y, kv.y, s[rr][r]));
            }
            float2 k8 = *(const float2*)&Ks[256 * LDK + d];
#pragma unroll
            for (int rr = 0; rr < G; rr++)
                s8[rr] = fmaf(q2[rr].x, k8.x, fmaf(q2[rr].y, k8.y, s8[rr]));
        }

#pragma unroll
        for (int rr = 0; rr < G; rr++) {
            float mx = s[rr][0];
#pragma unroll
            for (int r = 1; r < 8; r++) mx = fmaxf(mx, s[rr][r]);
#pragma unroll
            for (int off = 16; off > 0; off >>= 1)
                mx = fmaxf(mx, __shfl_xor_sync(0xffffffffu, mx, off));
            mx = fmaxf(mx, s8[rr]);

            float p[8], lsum = 0.f;
#pragma unroll
            for (int r = 0; r < 8; r++) { p[r] = __expf(s[rr][r] - mx); lsum += p[r]; }
#pragma unroll
            for (int off = 16; off > 0; off >>= 1)
                lsum += __shfl_xor_sync(0xffffffffu, lsum, off);
            const float p8  = __expf(s8[rr] - mx);
            const float inv = 1.f / (lsum + p8);

#pragma unroll
            for (int r = 0; r < 8; r++)
                Ps[(w * G + rr) * PLD + lane + (r << 5)] = p[r] * inv;
            if (lane == 0) Ps[(w * G + rr) * PLD + 256] = p8 * inv;
        }
        __syncwarp();

        float2 acc[G];
#pragma unroll
        for (int rr = 0; rr < G; rr++) acc[rr] = make_float2(0.f, 0.f);

        for (int j = 0; j < 256; j += 4) {
            float4 pr[G];
#pragma unroll
            for (int rr = 0; rr < G; rr++)
                pr[rr] = *(const float4*)&Ps[(w * G + rr) * PLD + j];
#pragma unroll
            for (int jj = 0; jj < 4; jj++) {
                float2 v = *(const float2*)&Vs[(j + jj) * LDK + dd];
#pragma unroll
                for (int rr = 0; rr < G; rr++) {
                    const float pv = (jj == 0) ? pr[rr].x : (jj == 1) ? pr[rr].y
                                   : (jj == 2) ? pr[rr].z : pr[rr].w;
                    acc[rr].x = fmaf(pv, v.x, acc[rr].x);
                    acc[rr].y = fmaf(pv, v.y, acc[rr].y);
                }
            }
        }
        {
            float2 v = *(const float2*)&Vs[256 * LDK + dd];
#pragma unroll
            for (int rr = 0; rr < G; rr++) {
                const float pv = Ps[(w * G + rr) * PLD + 256];
                acc[rr].x = fmaf(pv, v.x, acc[rr].x);
                acc[rr].y = fmaf(pv, v.y, acc[rr].y);
            }
        }

#pragma unroll
        for (int rr = 0; rr < G; rr++) {
            const int r = i0 + rr;
            if (r < SEQ)
                *(float2*)&g_ctx[base + (size_t)r * EMBED + dd] = acc[rr];
        }
        __syncwarp();
    }
}

// ===========================================================================
extern "C" void kernel_launch(void* const* d_in, const int* in_sizes, int n_in,
                              void* d_out, int out_size)
{
    const float* X  = (const float*)d_in[0];
    const float* Wq = (const float*)d_in[1];
    const float* bq = (const float*)d_in[2];
    const float* Wk = (const float*)d_in[3];
    const float* bk = (const float*)d_in[4];
    const float* Wv = (const float*)d_in[5];
    const float* bv = (const float*)d_in[6];
    const float* Wo = (const float*)d_in[7];
    const float* bo = (const float*)d_in[8];
    float* out = (float*)d_out;

    float *q, *k, *v, *ctx;
    cudaGetSymbolAddress((void**)&q,   g_q);
    cudaGetSymbolAddress((void**)&k,   g_k);
    cudaGetSymbolAddress((void**)&v,   g_v);
    cudaGetSymbolAddress((void**)&ctx, g_ctx);

    const dim3 gBlk(256);

    // fused Q/K/V projections (Q carries attention scale)
    const dim3 qkvGrid((M_ROWS + GBM - 1) / GBM, EMBED / GBN, 3);
    gemm_qkv_kernel<<<qkvGrid, gBlk>>>(X, Wq, bq, Wk, bk, Wv, bv, q, k, v);

    // attention
    const int smemBytes = (2 * SEQ * LDK + AW * G * 64 + AW * G * PLD) * (int)sizeof(float);
    cudaFuncSetAttribute(attn_kernel, cudaFuncAttributeMaxDynamicSharedMemorySize, smemBytes);
    attn_kernel<<<BATCH * HEADS, ATHR, smemBytes>>>();

    // output projection
    const dim3 oGrid((M_ROWS + GBM - 1) / GBM, EMBED / GBN);
    gemm_single_kernel<<<oGrid, gBlk>>>(ctx, Wo, bo, out, M_ROWS, 1.0f);
}

// round 12
// speedup vs baseline: 4.2509x; 1.3958x over previous
#include <cstdint>
#include <cstdio>
#include <cuda_runtime.h>
#include <cuda_fp16.h>
#include <math_constants.h>

// Problem constants
#define BATCH   32
#define SEQ     257
#define EMBED   1024
#define EMB2    512                  // EMBED/2 in u32 (packed half2)
#define HEADS   16
#define HEAD_D  64
#define M_ROWS  (BATCH * SEQ)        // 8224
#define ATTN_SCALE 0.125f

// Scratch (device globals; no allocation allowed)
__device__ float g_q[M_ROWS * EMBED];
__device__ float g_k[M_ROWS * EMBED];
__device__ float g_v[M_ROWS * EMBED];
__device__ float g_ctx[M_ROWS * EMBED];
// packed-fp16 copies (2 halves per u32)
__device__ uint32_t g_xh[M_ROWS * EMB2];
__device__ uint32_t g_ch[M_ROWS * EMB2];
__device__ uint32_t g_wh[4 * EMBED * EMB2];      // Wq, Wk, Wv, Wo

// ===========================================================================
// fp32 -> packed fp16 conversion
// ===========================================================================
__global__ __launch_bounds__(256)
void cvt_f16_kernel(const float* __restrict__ src, uint32_t* __restrict__ dst, int n4)
{
    int i = blockIdx.x * 256 + threadIdx.x;
    if (i >= n4) return;
    float4 x = ((const float4*)src)[i];
    __half2 lo = __floats2half2_rn(x.x, x.y);
    __half2 hi = __floats2half2_rn(x.z, x.w);
    ((uint2*)dst)[i] = make_uint2(*reinterpret_cast<uint32_t*>(&lo),
                                  *reinterpret_cast<uint32_t*>(&hi));
}

// ===========================================================================
// FP16 tensor-core GEMM:  C[m,n] = (sum_k A[m,k]*W[n,k] + bias[n]) * scale
// A,W pre-converted to packed fp16 (u32 = 2 halves). CTA tile 128x128,
// K-tile = 32 halves (16 u32), 256 thr (8 warps), warp tile 64x32,
// mma.sync.aligned.m16n8k16.row.col.f32.f16.f16.f32.
// Double-buffered smem, one __syncthreads per k-iteration.
// u32-granularity fragment layout identical to the tf32 m16n8k8 scheme:
//   a0=(g,t) a1=(g+8,t) a2=(g,t+4) a3=(g+8,t+4); b0/b1 = (row g, cols t/t+4)
// ===========================================================================
#define GBM 128
#define GBN 128
#define GS  24          // padded smem row stride (u32) -> conflict-free LDS.64

__device__ __forceinline__ void mma_f16(float& c0, float& c1, float& c2, float& c3,
                                        uint32_t a0, uint32_t a1, uint32_t a2, uint32_t a3,
                                        uint32_t b0, uint32_t b1) {
    asm volatile("mma.sync.aligned.m16n8k16.row.col.f32.f16.f16.f32 "
                 "{%0,%1,%2,%3}, {%4,%5,%6,%7}, {%8,%9}, {%0,%1,%2,%3};"
                 : "+f"(c0), "+f"(c1), "+f"(c2), "+f"(c3)
                 : "r"(a0), "r"(a1), "r"(a2), "r"(a3), "r"(b0), "r"(b1));
}

// u32 col c (0..15) -> permuted so (t, t+4) land adjacent -> LDS.64 frags
__device__ __forceinline__ int permcol(int c) {
    int k8 = c >> 3;
    int cc = c & 7;
    return (k8 << 3) + ((cc & 3) << 1) + (cc >> 2);
}

struct GemmSmem {
    uint32_t As[2][GBM * GS];
    uint32_t Bs[2][GBN * GS];
};

__device__ __forceinline__
void gemm_core(const uint32_t* __restrict__ A,     // [M, EMB2] packed fp16
               const uint32_t* __restrict__ W,     // [EMBED, EMB2] packed fp16
               const float* __restrict__ bias,
               float* __restrict__ C,
               int M, float scale, GemmSmem& sh)
{
    const int tid   = threadIdx.x;
    const int warp  = tid >> 5;
    const int lane  = tid & 31;
    const int warpM = warp >> 2;     // 0..1
    const int warpN = warp & 3;      // 0..3
    const int g     = lane >> 2;
    const int t     = lane & 3;

    const int m0 = blockIdx.x * GBM;
    const int n0 = blockIdx.y * GBN;

    const int r0 = tid >> 2;                 // rows r0 and r0+64
    const int c4 = (tid & 3) << 2;           // u32 col start (0,4,8,12)
    const bool aOk0 = (m0 + r0)      < M;
    const bool aOk1 = (m0 + r0 + 64) < M;

    int pc[4];
#pragma unroll
    for (int e = 0; e < 4; e++) pc[e] = permcol(c4 + e);

    float cacc[4][4][4];
#pragma unroll
    for (int i = 0; i < 4; i++)
#pragma unroll
        for (int j = 0; j < 4; j++)
#pragma unroll
            for (int e = 0; e < 4; e++) cacc[i][j][e] = 0.f;

    const uint4 z4 = make_uint4(0u, 0u, 0u, 0u);
    const uint32_t* pA0 = &A[(size_t)(m0 + r0)      * EMB2 + c4];
    const uint32_t* pA1 = &A[(size_t)(m0 + r0 + 64) * EMB2 + c4];
    const uint32_t* pB0 = &W[(size_t)(n0 + r0)      * EMB2 + c4];
    const uint32_t* pB1 = &W[(size_t)(n0 + r0 + 64) * EMB2 + c4];

    // prologue: k-tile 0 -> buffer 0
    {
        uint4 a0 = aOk0 ? *(const uint4*)pA0 : z4;
        uint4 a1 = aOk1 ? *(const uint4*)pA1 : z4;
        uint4 b0 = *(const uint4*)pB0;
        uint4 b1 = *(const uint4*)pB1;
        const uint32_t va0[4] = {a0.x, a0.y, a0.z, a0.w};
        const uint32_t va1[4] = {a1.x, a1.y, a1.z, a1.w};
        const uint32_t vb0[4] = {b0.x, b0.y, b0.z, b0.w};
        const uint32_t vb1[4] = {b1.x, b1.y, b1.z, b1.w};
#pragma unroll
        for (int e = 0; e < 4; e++) {
            sh.As[0][r0        * GS + pc[e]] = va0[e];
            sh.As[0][(r0 + 64) * GS + pc[e]] = va1[e];
            sh.Bs[0][r0        * GS + pc[e]] = vb0[e];
            sh.Bs[0][(r0 + 64) * GS + pc[e]] = vb1[e];
        }
    }
    __syncthreads();

    int p = 0;
    for (int kc = 0; kc < 32; kc++) {        // 32 k-tiles of 32 halves
        const bool more = (kc + 1 < 32);
        uint4 a0, a1, b0, b1;
        if (more) {
            const int kn = (kc + 1) * 16;    // u32 offset
            a0 = aOk0 ? *(const uint4*)(pA0 + kn) : z4;
            a1 = aOk1 ? *(const uint4*)(pA1 + kn) : z4;
            b0 = *(const uint4*)(pB0 + kn);
            b1 = *(const uint4*)(pB1 + kn);
        }

        // compute from buffer p: 2 k16 steps (u32 cols 0-7, 8-15)
        const uint32_t* Asp = sh.As[p];
        const uint32_t* Bsp = sh.Bs[p];
#pragma unroll
        for (int s = 0; s < 2; s++) {
            uint32_t af[4][4];
#pragma unroll
            for (int mt = 0; mt < 4; mt++) {
                const int row0 = warpM * 64 + mt * 16;
                uint2 lo = *(const uint2*)&Asp[(row0 + g)     * GS + s * 8 + 2 * t];
                uint2 hi = *(const uint2*)&Asp[(row0 + 8 + g) * GS + s * 8 + 2 * t];
                af[mt][0] = lo.x; af[mt][1] = hi.x; af[mt][2] = lo.y; af[mt][3] = hi.y;
            }
#pragma unroll
            for (int nt = 0; nt < 4; nt++) {
                const int nn0 = warpN * 32 + nt * 8;
                uint2 bb = *(const uint2*)&Bsp[(nn0 + g) * GS + s * 8 + 2 * t];
#pragma unroll
                for (int mt = 0; mt < 4; mt++) {
                    mma_f16(cacc[mt][nt][0], cacc[mt][nt][1], cacc[mt][nt][2], cacc[mt][nt][3],
                            af[mt][0], af[mt][1], af[mt][2], af[mt][3], bb.x, bb.y);
                }
            }
        }

        if (more) {
            uint32_t* Asn = sh.As[p ^ 1];
            uint32_t* Bsn = sh.Bs[p ^ 1];
            const uint32_t va0[4] = {a0.x, a0.y, a0.z, a0.w};
            const uint32_t va1[4] = {a1.x, a1.y, a1.z, a1.w};
            const uint32_t vb0[4] = {b0.x, b0.y, b0.z, b0.w};
            const uint32_t vb1[4] = {b1.x, b1.y, b1.z, b1.w};
#pragma unroll
            for (int e = 0; e < 4; e++) {
                Asn[r0        * GS + pc[e]] = va0[e];
                Asn[(r0 + 64) * GS + pc[e]] = va1[e];
                Bsn[r0        * GS + pc[e]] = vb0[e];
                Bsn[(r0 + 64) * GS + pc[e]] = vb1[e];
            }
            __syncthreads();
            p ^= 1;
        }
    }

    // epilogue: bias + scale
#pragma unroll
    for (int nt = 0; nt < 4; nt++) {
        const int col = n0 + warpN * 32 + nt * 8 + 2 * t;
        const float bn0 = bias[col];
        const float bn1 = bias[col + 1];
#pragma unroll
        for (int mt = 0; mt < 4; mt++) {
            const int row  = m0 + warpM * 64 + mt * 16 + g;
            const int row2 = row + 8;
            if (row < M) {
                float2 o = make_float2((cacc[mt][nt][0] + bn0) * scale,
                                       (cacc[mt][nt][1] + bn1) * scale);
                *(float2*)&C[(size_t)row * EMBED + col] = o;
            }
            if (row2 < M) {
                float2 o = make_float2((cacc[mt][nt][2] + bn0) * scale,
                                       (cacc[mt][nt][3] + bn1) * scale);
                *(float2*)&C[(size_t)row2 * EMBED + col] = o;
            }
        }
    }
}

// Fused QKV: blockIdx.z selects {Wq,Wk,Wv} plane in g_wh.
__global__ __launch_bounds__(256, 2)
void gemm_qkv_kernel(const uint32_t* __restrict__ X,
                     const uint32_t* __restrict__ Wall,
                     const float* __restrict__ bq, const float* __restrict__ bk,
                     const float* __restrict__ bv,
                     float* __restrict__ q, float* __restrict__ k, float* __restrict__ v)
{
    __shared__ GemmSmem sh;
    const int z = blockIdx.z;
    const float* bias = (z == 0) ? bq : (z == 1) ? bk : bv;
    float*       C    = (z == 0) ? q  : (z == 1) ? k  : v;
    const float scale = (z == 0) ? ATTN_SCALE : 1.0f;
    gemm_core(X, Wall + (size_t)z * EMBED * EMB2, bias, C, M_ROWS, scale, sh);
}

__global__ __launch_bounds__(256, 2)
void gemm_single_kernel(const uint32_t* __restrict__ A, const uint32_t* __restrict__ W,
                        const float* __restrict__ bias, float* __restrict__ C,
                        int M, float scale)
{
    __shared__ GemmSmem sh;
    gemm_core(A, W, bias, C, M, scale, sh);
}

// ===========================================================================
// Attention (unchanged): one CTA per (b,h), 16 warps, G=4 rows/warp.
// ===========================================================================
#define AW   16
#define ATHR 512
#define LDK  66
#define PLD  260
#define G    4

__global__ __launch_bounds__(ATHR, 1)
void attn_kernel()
{
    extern __shared__ float sm[];
    float* Ks = sm;
    float* Vs = Ks + SEQ * LDK;
    float* Qs = Vs + SEQ * LDK;
    float* Ps = Qs + AW * G * 64;

    const int tid  = threadIdx.x;
    const int w    = tid >> 5;
    const int lane = tid & 31;
    const int b = blockIdx.x >> 4;
    const int h = blockIdx.x & 15;

    const size_t base = (size_t)b * SEQ * EMBED + h * HEAD_D;

    for (int idx = tid; idx < SEQ * 16; idx += ATHR) {
        const int j = idx >> 4;
        const int c = (idx & 15) << 2;
        float4 fk = *(const float4*)&g_k[base + (size_t)j * EMBED + c];
        float4 fv = *(const float4*)&g_v[base + (size_t)j * EMBED + c];
        float* dk = &Ks[j * LDK + c];
        float* dv = &Vs[j * LDK + c];
        dk[0] = fk.x; dk[1] = fk.y; dk[2] = fk.z; dk[3] = fk.w;
        dv[0] = fv.x; dv[1] = fv.y; dv[2] = fv.z; dv[3] = fv.w;
    }
    __syncthreads();

    const int dd = lane * 2;

    for (int i0 = w * G; i0 < SEQ; i0 += AW * G) {
#pragma unroll
        for (int rr = 0; rr < G; rr++) {
            int r = i0 + rr;
            if (r >= SEQ) r = SEQ - 1;
            Qs[(w * G + rr) * 64 + lane]      = g_q[base + (size_t)r * EMBED + lane];
            Qs[(w * G + rr) * 64 + lane + 32] = g_q[base + (size_t)r * EMBED + lane + 32];
        }
        __syncwarp();

        float s[G][8];
        float s8[G];
#pragma unroll
        for (int rr = 0; rr < G; rr++) {
            s8[rr] = 0.f;
#pragma unroll
            for (int r = 0; r < 8; r++) s[rr][r] = 0.f;
        }

#pragma unroll 2
        for (int d2 = 0; d2 < 32; d2++) {
            const int d = d2 << 1;
            float2 q2[G];
#pragma unroll
            for (int rr = 0; rr < G; rr++)
                q2[rr] = *(const float2*)&Qs[(w * G + rr) * 64 + d];
#pragma unroll
            for (int r = 0; r < 8; r++) {
                float2 kv = *(const float2*)&Ks[(lane + (r << 5)) * LDK + d];
#pragma unroll
                for (int rr = 0; rr < G; rr++)
                    s[rr][r] = fmaf(q2[rr].x, kv.x, fmaf(q2[rr].y, kv.y, s[rr][r]));
            }
            float2 k8 = *(const float2*)&Ks[256 * LDK + d];
#pragma unroll
            for (int rr = 0; rr < G; rr++)
                s8[rr] = fmaf(q2[rr].x, k8.x, fmaf(q2[rr].y, k8.y, s8[rr]));
        }

#pragma unroll
        for (int rr = 0; rr < G; rr++) {
            float mx = s[rr][0];
#pragma unroll
            for (int r = 1; r < 8; r++) mx = fmaxf(mx, s[rr][r]);
#pragma unroll
            for (int off = 16; off > 0; off >>= 1)
                mx = fmaxf(mx, __shfl_xor_sync(0xffffffffu, mx, off));
            mx = fmaxf(mx, s8[rr]);

            float p[8], lsum = 0.f;
#pragma unroll
            for (int r = 0; r < 8; r++) { p[r] = __expf(s[rr][r] - mx); lsum += p[r]; }
#pragma unroll
            for (int off = 16; off > 0; off >>= 1)
                lsum += __shfl_xor_sync(0xffffffffu, lsum, off);
            const float p8  = __expf(s8[rr] - mx);
            const float inv = 1.f / (lsum + p8);

#pragma unroll
            for (int r = 0; r < 8; r++)
                Ps[(w * G + rr) * PLD + lane + (r << 5)] = p[r] * inv;
            if (lane == 0) Ps[(w * G + rr) * PLD + 256] = p8 * inv;
        }
        __syncwarp();

        float2 acc[G];
#pragma unroll
        for (int rr = 0; rr < G; rr++) acc[rr] = make_float2(0.f, 0.f);

        for (int j = 0; j < 256; j += 4) {
            float4 pr[G];
#pragma unroll
            for (int rr = 0; rr < G; rr++)
                pr[rr] = *(const float4*)&Ps[(w * G + rr) * PLD + j];
#pragma unroll
            for (int jj = 0; jj < 4; jj++) {
                float2 v = *(const float2*)&Vs[(j + jj) * LDK + dd];
#pragma unroll
                for (int rr = 0; rr < G; rr++) {
                    const float pv = (jj == 0) ? pr[rr].x : (jj == 1) ? pr[rr].y
                                   : (jj == 2) ? pr[rr].z : pr[rr].w;
                    acc[rr].x = fmaf(pv, v.x, acc[rr].x);
                    acc[rr].y = fmaf(pv, v.y, acc[rr].y);
                }
            }
        }
        {
            float2 v = *(const float2*)&Vs[256 * LDK + dd];
#pragma unroll
            for (int rr = 0; rr < G; rr++) {
                const float pv = Ps[(w * G + rr) * PLD + 256];
                acc[rr].x = fmaf(pv, v.x, acc[rr].x);
                acc[rr].y = fmaf(pv, v.y, acc[rr].y);
            }
        }

#pragma unroll
        for (int rr = 0; rr < G; rr++) {
            const int r = i0 + rr;
            if (r < SEQ)
                *(float2*)&g_ctx[base + (size_t)r * EMBED + dd] = acc[rr];
        }
        __syncwarp();
    }
}

// ===========================================================================
extern "C" void kernel_launch(void* const* d_in, const int* in_sizes, int n_in,
                              void* d_out, int out_size)
{
    const float* X  = (const float*)d_in[0];
    const float* Wq = (const float*)d_in[1];
    const float* bq = (const float*)d_in[2];
    const float* Wk = (const float*)d_in[3];
    const float* bk = (const float*)d_in[4];
    const float* Wv = (const float*)d_in[5];
    const float* bv = (const float*)d_in[6];
    const float* Wo = (const float*)d_in[7];
    const float* bo = (const float*)d_in[8];
    float* out = (float*)d_out;

    float *q, *k, *v, *ctx;
    uint32_t *xh, *ch, *wh;
    cudaGetSymbolAddress((void**)&q,   g_q);
    cudaGetSymbolAddress((void**)&k,   g_k);
    cudaGetSymbolAddress((void**)&v,   g_v);
    cudaGetSymbolAddress((void**)&ctx, g_ctx);
    cudaGetSymbolAddress((void**)&xh,  g_xh);
    cudaGetSymbolAddress((void**)&ch,  g_ch);
    cudaGetSymbolAddress((void**)&wh,  g_wh);

    const int WPLANE = EMBED * EMB2;            // u32 per weight plane
    const int n4x = M_ROWS * EMBED / 4;         // 2105344
    const int n4w = EMBED * EMBED / 4;          // 262144

    // 1. pack X and the four weight matrices to fp16
    cvt_f16_kernel<<<(n4x + 255) / 256, 256>>>(X,  xh, n4x);
    cvt_f16_kernel<<<(n4w + 255) / 256, 256>>>(Wq, wh + 0 * WPLANE, n4w);
    cvt_f16_kernel<<<(n4w + 255) / 256, 256>>>(Wk, wh + 1 * WPLANE, n4w);
    cvt_f16_kernel<<<(n4w + 255) / 256, 256>>>(Wv, wh + 2 * WPLANE, n4w);
    cvt_f16_kernel<<<(n4w + 255) / 256, 256>>>(Wo, wh + 3 * WPLANE, n4w);

    // 2. fused Q/K/V projections (Q carries attention scale)
    const dim3 gBlk(256);
    const dim3 qkvGrid((M_ROWS + GBM - 1) / GBM, EMBED / GBN, 3);
    gemm_qkv_kernel<<<qkvGrid, gBlk>>>(xh, wh, bq, bk, bv, q, k, v);

    // 3. attention
    const int smemBytes = (2 * SEQ * LDK + AW * G * 64 + AW * G * PLD) * (int)sizeof(float);
    cudaFuncSetAttribute(attn_kernel, cudaFuncAttributeMaxDynamicSharedMemorySize, smemBytes);
    attn_kernel<<<BATCH * HEADS, ATHR, smemBytes>>>();

    // 4. pack ctx, then output projection
    cvt_f16_kernel<<<(n4x + 255) / 256, 256>>>(ctx, ch, n4x);
    const dim3 oGrid((M_ROWS + GBM - 1) / GBM, EMBED / GBN);
    gemm_single_kernel<<<oGrid, gBlk>>>(ch, wh + 3 * WPLANE, bo, out, M_ROWS, 1.0f);
}

// round 14
// speedup vs baseline: 6.2570x; 1.4719x over previous
#include <cstdint>
#include <cstdio>
#include <cuda_runtime.h>
#include <cuda_fp16.h>
#include <math_constants.h>

// Problem constants
#define BATCH   32
#define SEQ     257
#define EMBED   1024
#define EMB2    512                  // EMBED/2 in u32 (packed half2)
#define HEADS   16
#define HEAD_D  64
#define M_ROWS  (BATCH * SEQ)        // 8224
#define ATTN_SCALE 0.125f

// Scratch (device globals; no allocation allowed)
__device__ uint32_t g_qh[M_ROWS * EMB2];         // Q packed fp16 (scaled)
__device__ uint32_t g_kh[M_ROWS * EMB2];         // K packed fp16
__device__ uint32_t g_vh[M_ROWS * EMB2];         // V packed fp16
__device__ uint32_t g_ch[M_ROWS * EMB2];         // ctx packed fp16
__device__ uint32_t g_xh[M_ROWS * EMB2];         // X packed fp16
__device__ uint32_t g_wh[4 * EMBED * EMB2];      // Wq, Wk, Wv, Wo packed fp16

__device__ __forceinline__ uint32_t packh2(float a, float b) {
    __half2 hh = __floats2half2_rn(a, b);
    return *reinterpret_cast<uint32_t*>(&hh);
}

// ===========================================================================
// fp32 -> packed fp16 conversion
// ===========================================================================
__global__ __launch_bounds__(256)
void cvt_f16_kernel(const float* __restrict__ src, uint32_t* __restrict__ dst, int n4)
{
    int i = blockIdx.x * 256 + threadIdx.x;
    if (i >= n4) return;
    float4 x = ((const float4*)src)[i];
    ((uint2*)dst)[i] = make_uint2(packh2(x.x, x.y), packh2(x.z, x.w));
}

// ===========================================================================
// FP16 tensor-core GEMM (m16n8k16), CTA 128x128, 8 warps, warp tile 64x32.
// Double-buffered smem; optionally writes packed-fp16 output (HOUT).
// ===========================================================================
#define GBM 128
#define GBN 128
#define GS  24          // padded smem row stride (u32) -> conflict-free LDS.64

__device__ __forceinline__ void mma_f16(float& c0, float& c1, float& c2, float& c3,
                                        uint32_t a0, uint32_t a1, uint32_t a2, uint32_t a3,
                                        uint32_t b0, uint32_t b1) {
    asm volatile("mma.sync.aligned.m16n8k16.row.col.f32.f16.f16.f32 "
                 "{%0,%1,%2,%3}, {%4,%5,%6,%7}, {%8,%9}, {%0,%1,%2,%3};"
                 : "+f"(c0), "+f"(c1), "+f"(c2), "+f"(c3)
                 : "r"(a0), "r"(a1), "r"(a2), "r"(a3), "r"(b0), "r"(b1));
}

__device__ __forceinline__ int permcol(int c) {
    int k8 = c >> 3;
    int cc = c & 7;
    return (k8 << 3) + ((cc & 3) << 1) + (cc >> 2);
}

struct GemmSmem {
    uint32_t As[2][GBM * GS];
    uint32_t Bs[2][GBN * GS];
};

template <bool HOUT>
__device__ __forceinline__
void gemm_core(const uint32_t* __restrict__ A,     // [M, EMB2] packed fp16
               const uint32_t* __restrict__ W,     // [EMBED, EMB2] packed fp16
               const float* __restrict__ bias,
               void* __restrict__ Cout,
               int M, float scale, GemmSmem& sh)
{
    const int tid   = threadIdx.x;
    const int warp  = tid >> 5;
    const int lane  = tid & 31;
    const int warpM = warp >> 2;
    const int warpN = warp & 3;
    const int g     = lane >> 2;
    const int t     = lane & 3;

    const int m0 = blockIdx.x * GBM;
    const int n0 = blockIdx.y * GBN;

    const int r0 = tid >> 2;
    const int c4 = (tid & 3) << 2;
    const bool aOk0 = (m0 + r0)      < M;
    const bool aOk1 = (m0 + r0 + 64) < M;

    int pc[4];
#pragma unroll
    for (int e = 0; e < 4; e++) pc[e] = permcol(c4 + e);

    float cacc[4][4][4];
#pragma unroll
    for (int i = 0; i < 4; i++)
#pragma unroll
        for (int j = 0; j < 4; j++)
#pragma unroll
            for (int e = 0; e < 4; e++) cacc[i][j][e] = 0.f;

    const uint4 z4 = make_uint4(0u, 0u, 0u, 0u);
    const uint32_t* pA0 = &A[(size_t)(m0 + r0)      * EMB2 + c4];
    const uint32_t* pA1 = &A[(size_t)(m0 + r0 + 64) * EMB2 + c4];
    const uint32_t* pB0 = &W[(size_t)(n0 + r0)      * EMB2 + c4];
    const uint32_t* pB1 = &W[(size_t)(n0 + r0 + 64) * EMB2 + c4];

    {
        uint4 a0 = aOk0 ? *(const uint4*)pA0 : z4;
        uint4 a1 = aOk1 ? *(const uint4*)pA1 : z4;
        uint4 b0 = *(const uint4*)pB0;
        uint4 b1 = *(const uint4*)pB1;
        const uint32_t va0[4] = {a0.x, a0.y, a0.z, a0.w};
        const uint32_t va1[4] = {a1.x, a1.y, a1.z, a1.w};
        const uint32_t vb0[4] = {b0.x, b0.y, b0.z, b0.w};
        const uint32_t vb1[4] = {b1.x, b1.y, b1.z, b1.w};
#pragma unroll
        for (int e = 0; e < 4; e++) {
            sh.As[0][r0        * GS + pc[e]] = va0[e];
            sh.As[0][(r0 + 64) * GS + pc[e]] = va1[e];
            sh.Bs[0][r0        * GS + pc[e]] = vb0[e];
            sh.Bs[0][(r0 + 64) * GS + pc[e]] = vb1[e];
        }
    }
    __syncthreads();

    int p = 0;
    for (int kc = 0; kc < 32; kc++) {
        const bool more = (kc + 1 < 32);
        uint4 a0, a1, b0, b1;
        if (more) {
            const int kn = (kc + 1) * 16;
            a0 = aOk0 ? *(const uint4*)(pA0 + kn) : z4;
            a1 = aOk1 ? *(const uint4*)(pA1 + kn) : z4;
            b0 = *(const uint4*)(pB0 + kn);
            b1 = *(const uint4*)(pB1 + kn);
        }

        const uint32_t* Asp = sh.As[p];
        const uint32_t* Bsp = sh.Bs[p];
#pragma unroll
        for (int s = 0; s < 2; s++) {
            uint32_t af[4][4];
#pragma unroll
            for (int mt = 0; mt < 4; mt++) {
                const int row0 = warpM * 64 + mt * 16;
                uint2 lo = *(const uint2*)&Asp[(row0 + g)     * GS + s * 8 + 2 * t];
                uint2 hi = *(const uint2*)&Asp[(row0 + 8 + g) * GS + s * 8 + 2 * t];
                af[mt][0] = lo.x; af[mt][1] = hi.x; af[mt][2] = lo.y; af[mt][3] = hi.y;
            }
#pragma unroll
            for (int nt = 0; nt < 4; nt++) {
                const int nn0 = warpN * 32 + nt * 8;
                uint2 bb = *(const uint2*)&Bsp[(nn0 + g) * GS + s * 8 + 2 * t];
#pragma unroll
                for (int mt = 0; mt < 4; mt++) {
                    mma_f16(cacc[mt][nt][0], cacc[mt][nt][1], cacc[mt][nt][2], cacc[mt][nt][3],
                            af[mt][0], af[mt][1], af[mt][2], af[mt][3], bb.x, bb.y);
                }
            }
        }

        if (more) {
            uint32_t* Asn = sh.As[p ^ 1];
            uint32_t* Bsn = sh.Bs[p ^ 1];
            const uint32_t va0[4] = {a0.x, a0.y, a0.z, a0.w};
            const uint32_t va1[4] = {a1.x, a1.y, a1.z, a1.w};
            const uint32_t vb0[4] = {b0.x, b0.y, b0.z, b0.w};
            const uint32_t vb1[4] = {b1.x, b1.y, b1.z, b1.w};
#pragma unroll
            for (int e = 0; e < 4; e++) {
                Asn[r0        * GS + pc[e]] = va0[e];
                Asn[(r0 + 64) * GS + pc[e]] = va1[e];
                Bsn[r0        * GS + pc[e]] = vb0[e];
                Bsn[(r0 + 64) * GS + pc[e]] = vb1[e];
            }
            __syncthreads();
            p ^= 1;
        }
    }

    // epilogue
#pragma unroll
    for (int nt = 0; nt < 4; nt++) {
        const int col = n0 + warpN * 32 + nt * 8 + 2 * t;   // even
        const float bn0 = bias[col];
        const float bn1 = bias[col + 1];
#pragma unroll
        for (int mt = 0; mt < 4; mt++) {
            const int row  = m0 + warpM * 64 + mt * 16 + g;
            const int row2 = row + 8;
            if (HOUT) {
                uint32_t* CH = (uint32_t*)Cout;
                if (row < M)
                    CH[(size_t)row * EMB2 + (col >> 1)] =
                        packh2((cacc[mt][nt][0] + bn0) * scale, (cacc[mt][nt][1] + bn1) * scale);
                if (row2 < M)
                    CH[(size_t)row2 * EMB2 + (col >> 1)] =
                        packh2((cacc[mt][nt][2] + bn0) * scale, (cacc[mt][nt][3] + bn1) * scale);
            } else {
                float* CF = (float*)Cout;
                if (row < M) {
                    float2 o = make_float2((cacc[mt][nt][0] + bn0) * scale,
                                           (cacc[mt][nt][1] + bn1) * scale);
                    *(float2*)&CF[(size_t)row * EMBED + col] = o;
                }
                if (row2 < M) {
                    float2 o = make_float2((cacc[mt][nt][2] + bn0) * scale,
                                           (cacc[mt][nt][3] + bn1) * scale);
                    *(float2*)&CF[(size_t)row2 * EMBED + col] = o;
                }
            }
        }
    }
}

// Fused QKV (fp16 output): blockIdx.z selects {Wq,Wk,Wv}.
__global__ __launch_bounds__(256, 2)
void gemm_qkv_kernel(const uint32_t* __restrict__ X,
                     const uint32_t* __restrict__ Wall,
                     const float* __restrict__ bq, const float* __restrict__ bk,
                     const float* __restrict__ bv,
                     uint32_t* __restrict__ q, uint32_t* __restrict__ k, uint32_t* __restrict__ v)
{
    __shared__ GemmSmem sh;
    const int z = blockIdx.z;
    const float* bias = (z == 0) ? bq : (z == 1) ? bk : bv;
    uint32_t*    C    = (z == 0) ? q  : (z == 1) ? k  : v;
    const float scale = (z == 0) ? ATTN_SCALE : 1.0f;
    gemm_core<true>(X, Wall + (size_t)z * EMBED * EMB2, bias, C, M_ROWS, scale, sh);
}

// Output projection (fp32 output)
__global__ __launch_bounds__(256, 2)
void gemm_single_kernel(const uint32_t* __restrict__ A, const uint32_t* __restrict__ W,
                        const float* __restrict__ bias, float* __restrict__ C,
                        int M, float scale)
{
    __shared__ GemmSmem sh;
    gemm_core<false>(A, W, bias, C, M, scale, sh);
}

// ===========================================================================
// Tensor-core attention: one CTA per (b,h), 256 thr (8 warps).
// Each warp owns 16 query rows; flash-style online softmax over chunks of
// 32 keys; S and PV via m16n8k16 fp16 mma, fp32 accumulators in registers.
// Q/K staged row-major (stride 72 halves, conflict-free frag loads);
// V staged transposed (Vt[dim][key], stride 296). ctx written packed fp16.
// ===========================================================================
#define SEQP  288          // 9 chunks of 32 keys
#define QROWS 272          // 17 row tiles of 16
#define QSTR  72
#define KSTR  72
#define VSTR  296
#define NCHUNK 9

__global__ __launch_bounds__(256, 1)
void attn_mma_kernel()
{
    extern __shared__ __half smh[];
    __half* Qh = smh;                       // QROWS * QSTR
    __half* Kh = Qh + QROWS * QSTR;         // SEQP * KSTR
    __half* Vt = Kh + SEQP * KSTR;          // 64 * VSTR

    const int tid  = threadIdx.x;
    const int w    = tid >> 5;
    const int lane = tid & 31;
    const int g    = lane >> 2;
    const int t    = lane & 3;
    const int b = blockIdx.x >> 4;
    const int h = blockIdx.x & 15;

    const size_t base2 = (size_t)b * SEQ * EMB2 + h * 32;   // u32 offset of this head

    // stage Q (u32 copies, rows >= SEQ replicate row 0: finite, masked at store)
    for (int idx = tid; idx < QROWS * 32; idx += 256) {
        const int r = idx >> 5, c = idx & 31;
        const int rs = (r < SEQ) ? r : 0;
        *(uint32_t*)&Qh[r * QSTR + c * 2] = g_qh[base2 + (size_t)rs * EMB2 + c];
    }
    // stage K
    for (int idx = tid; idx < SEQP * 32; idx += 256) {
        const int r = idx >> 5, c = idx & 31;
        const int rs = (r < SEQ) ? r : 0;
        *(uint32_t*)&Kh[r * KSTR + c * 2] = g_kh[base2 + (size_t)rs * EMB2 + c];
    }
    // stage V transposed: Vt[dim][key]
    for (int idx = tid; idx < SEQP * 32; idx += 256) {
        const int j = idx >> 5, c = idx & 31;
        const int js = (j < SEQ) ? j : 0;
        const uint32_t v2 = g_vh[base2 + (size_t)js * EMB2 + c];
        const __half2 hv = *reinterpret_cast<const __half2*>(&v2);
        Vt[(2 * c)     * VSTR + j] = __low2half(hv);
        Vt[(2 * c + 1) * VSTR + j] = __high2half(hv);
    }
    __syncthreads();

    for (int tile = w; tile < 17; tile += 8) {
        const int rb = tile * 16;

        // Q fragments: 4 k-steps of m16k16
        uint32_t qf[4][4];
#pragma unroll
        for (int ks = 0; ks < 4; ks++) {
            const __half* qp  = &Qh[(rb + g) * QSTR + ks * 16 + 2 * t];
            const __half* qp8 = qp + 8 * QSTR;
            qf[ks][0] = *(const uint32_t*)qp;
            qf[ks][1] = *(const uint32_t*)qp8;
            qf[ks][2] = *(const uint32_t*)(qp + 8);
            qf[ks][3] = *(const uint32_t*)(qp8 + 8);
        }

        float of[8][4];
#pragma unroll
        for (int dn = 0; dn < 8; dn++)
#pragma unroll
            for (int e = 0; e < 4; e++) of[dn][e] = 0.f;
        float m0 = -1e30f, m1 = -1e30f, l0 = 0.f, l1 = 0.f;

        for (int cb = 0; cb < NCHUNK; cb++) {
            const int kb = cb * 32;

            // S chunk: 4 n-tiles x 4 k-steps
            float sf[4][4];
#pragma unroll
            for (int nt = 0; nt < 4; nt++)
#pragma unroll
                for (int e = 0; e < 4; e++) sf[nt][e] = 0.f;

#pragma unroll
            for (int nt = 0; nt < 4; nt++) {
                const __half* kp0 = &Kh[(kb + nt * 8 + g) * KSTR + 2 * t];
#pragma unroll
                for (int ks = 0; ks < 4; ks++) {
                    const uint32_t b0 = *(const uint32_t*)(kp0 + ks * 16);
                    const uint32_t b1 = *(const uint32_t*)(kp0 + ks * 16 + 8);
                    mma_f16(sf[nt][0], sf[nt][1], sf[nt][2], sf[nt][3],
                            qf[ks][0], qf[ks][1], qf[ks][2], qf[ks][3], b0, b1);
                }
            }

            // mask padded keys (last chunk covers cols 256..287; only 256 valid)
            if (cb == NCHUNK - 1) {
#pragma unroll
                for (int nt = 0; nt < 4; nt++) {
                    const int c0 = 256 + nt * 8 + 2 * t;
                    if (c0     >= SEQ) { sf[nt][0] = -1e30f; sf[nt][2] = -1e30f; }
                    if (c0 + 1 >= SEQ) { sf[nt][1] = -1e30f; sf[nt][3] = -1e30f; }
                }
            }

            // online softmax
            float cm0 = sf[0][0], cm1 = sf[0][2];
#pragma unroll
            for (int nt = 0; nt < 4; nt++) {
                cm0 = fmaxf(cm0, fmaxf(sf[nt][0], sf[nt][1]));
                cm1 = fmaxf(cm1, fmaxf(sf[nt][2], sf[nt][3]));
            }
            cm0 = fmaxf(cm0, __shfl_xor_sync(0xffffffffu, cm0, 1));
            cm0 = fmaxf(cm0, __shfl_xor_sync(0xffffffffu, cm0, 2));
            cm1 = fmaxf(cm1, __shfl_xor_sync(0xffffffffu, cm1, 1));
            cm1 = fmaxf(cm1, __shfl_xor_sync(0xffffffffu, cm1, 2));

            const float mn0 = fmaxf(m0, cm0);
            const float mn1 = fmaxf(m1, cm1);
            const float a0 = __expf(m0 - mn0);
            const float a1 = __expf(m1 - mn1);
            m0 = mn0; m1 = mn1;

            float ps0 = 0.f, ps1 = 0.f;
#pragma unroll
            for (int nt = 0; nt < 4; nt++) {
                sf[nt][0] = __expf(sf[nt][0] - m0); ps0 += sf[nt][0];
                sf[nt][1] = __expf(sf[nt][1] - m0); ps0 += sf[nt][1];
                sf[nt][2] = __expf(sf[nt][2] - m1); ps1 += sf[nt][2];
                sf[nt][3] = __expf(sf[nt][3] - m1); ps1 += sf[nt][3];
            }
            l0 = l0 * a0 + ps0;
            l1 = l1 * a1 + ps1;

#pragma unroll
            for (int dn = 0; dn < 8; dn++) {
                of[dn][0] *= a0; of[dn][1] *= a0;
                of[dn][2] *= a1; of[dn][3] *= a1;
            }

            // P as fp16 A-fragments (C-frag layout == A-frag layout)
            uint32_t pf[2][4];
#pragma unroll
            for (int ks = 0; ks < 2; ks++) {
                pf[ks][0] = packh2(sf[2 * ks][0],     sf[2 * ks][1]);
                pf[ks][1] = packh2(sf[2 * ks][2],     sf[2 * ks][3]);
                pf[ks][2] = packh2(sf[2 * ks + 1][0], sf[2 * ks + 1][1]);
                pf[ks][3] = packh2(sf[2 * ks + 1][2], sf[2 * ks + 1][3]);
            }

            // O += P * V
#pragma unroll
            for (int dn = 0; dn < 8; dn++) {
                const __half* vp0 = &Vt[(dn * 8 + g) * VSTR + kb + 2 * t];
#pragma unroll
                for (int ks = 0; ks < 2; ks++) {
                    const uint32_t b0 = *(const uint32_t*)(vp0 + ks * 16);
                    const uint32_t b1 = *(const uint32_t*)(vp0 + ks * 16 + 8);
                    mma_f16(of[dn][0], of[dn][1], of[dn][2], of[dn][3],
                            pf[ks][0], pf[ks][1], pf[ks][2], pf[ks][3], b0, b1);
                }
            }
        }

        // finalize: reduce l over quad, normalize, store packed fp16
        l0 += __shfl_xor_sync(0xffffffffu, l0, 1);
        l0 += __shfl_xor_sync(0xffffffffu, l0, 2);
        l1 += __shfl_xor_sync(0xffffffffu, l1, 1);
        l1 += __shfl_xor_sync(0xffffffffu, l1, 2);
        const float inv0 = 1.f / l0;
        const float inv1 = 1.f / l1;

        const int r0 = rb + g;
        const int r1 = rb + g + 8;
#pragma unroll
        for (int dn = 0; dn < 8; dn++) {
            const size_t cidx = (size_t)h * 32 + dn * 4 + t;   // u32 col within row
            if (r0 < SEQ)
                g_ch[((size_t)b * SEQ + r0) * EMB2 + cidx] =
                    packh2(of[dn][0] * inv0, of[dn][1] * inv0);
            if (r1 < SEQ)
                g_ch[((size_t)b * SEQ + r1) * EMB2 + cidx] =
                    packh2(of[dn][2] * inv1, of[dn][3] * inv1);
        }
    }
}

// ===========================================================================
extern "C" void kernel_launch(void* const* d_in, const int* in_sizes, int n_in,
                              void* d_out, int out_size)
{
    const float* X  = (const float*)d_in[0];
    const float* Wq = (const float*)d_in[1];
    const float* bq = (const float*)d_in[2];
    const float* Wk = (const float*)d_in[3];
    const float* bk = (const float*)d_in[4];
    const float* Wv = (const float*)d_in[5];
    const float* bv = (const float*)d_in[6];
    const float* Wo = (const float*)d_in[7];
    const float* bo = (const float*)d_in[8];
    float* out = (float*)d_out;

    uint32_t *qh, *kh, *vh, *ch, *xh, *wh;
    cudaGetSymbolAddress((void**)&qh, g_qh);
    cudaGetSymbolAddress((void**)&kh, g_kh);
    cudaGetSymbolAddress((void**)&vh, g_vh);
    cudaGetSymbolAddress((void**)&ch, g_ch);
    cudaGetSymbolAddress((void**)&xh, g_xh);
    cudaGetSymbolAddress((void**)&wh, g_wh);

    const int WPLANE = EMBED * EMB2;
    const int n4x = M_ROWS * EMBED / 4;
    const int n4w = EMBED * EMBED / 4;

    // 1. pack X and the four weight matrices to fp16
    cvt_f16_kernel<<<(n4x + 255) / 256, 256>>>(X,  xh, n4x);
    cvt_f16_kernel<<<(n4w + 255) / 256, 256>>>(Wq, wh + 0 * WPLANE, n4w);
    cvt_f16_kernel<<<(n4w + 255) / 256, 256>>>(Wk, wh + 1 * WPLANE, n4w);
    cvt_f16_kernel<<<(n4w + 255) / 256, 256>>>(Wv, wh + 2 * WPLANE, n4w);
    cvt_f16_kernel<<<(n4w + 255) / 256, 256>>>(Wo, wh + 3 * WPLANE, n4w);

    // 2. fused Q/K/V projections -> packed fp16 (Q carries attention scale)
    const dim3 gBlk(256);
    const dim3 qkvGrid((M_ROWS + GBM - 1) / GBM, EMBED / GBN, 3);
    gemm_qkv_kernel<<<qkvGrid, gBlk>>>(xh, wh, bq, bk, bv, qh, kh, vh);

    // 3. tensor-core attention -> ctx packed fp16
    const int smemBytes = (QROWS * QSTR + SEQP * KSTR + 64 * VSTR) * (int)sizeof(__half);
    cudaFuncSetAttribute(attn_mma_kernel, cudaFuncAttributeMaxDynamicSharedMemorySize, smemBytes);
    attn_mma_kernel<<<BATCH * HEADS, 256, smemBytes>>>();

    // 4. output projection (fp32 out)
    const dim3 oGrid((M_ROWS + GBM - 1) / GBM, EMBED / GBN);
    gemm_single_kernel<<<oGrid, gBlk>>>(ch, wh + 3 * WPLANE, bo, out, M_ROWS, 1.0f);
}

// round 16
// speedup vs baseline: 6.4684x; 1.0338x over previous
#include <cstdint>
#include <cstdio>
#include <cuda_runtime.h>
#include <cuda_fp16.h>
#include <math_constants.h>

// Problem constants
#define BATCH   32
#define SEQ     257
#define EMBED   1024
#define EMB2    512                  // EMBED/2 in u32 (packed half2)
#define HEADS   16
#define HEAD_D  64
#define M_ROWS  (BATCH * SEQ)        // 8224
#define ATTN_SCALE 0.125f

// Scratch (device globals; no allocation allowed)
__device__ uint32_t g_qh[M_ROWS * EMB2];         // Q packed fp16 (scaled)
__device__ uint32_t g_kh[M_ROWS * EMB2];         // K packed fp16
__device__ uint32_t g_vh[M_ROWS * EMB2];         // V packed fp16
__device__ uint32_t g_ch[M_ROWS * EMB2];         // ctx packed fp16
__device__ uint32_t g_xh[M_ROWS * EMB2];         // X packed fp16
__device__ uint32_t g_wh[4 * EMBED * EMB2];      // Wq, Wk, Wv, Wo packed fp16

__device__ __forceinline__ uint32_t packh2(float a, float b) {
    __half2 hh = __floats2half2_rn(a, b);
    return *reinterpret_cast<uint32_t*>(&hh);
}

// ===========================================================================
// fp32 -> packed fp16 conversion
// ===========================================================================
__global__ __launch_bounds__(256)
void cvt_f16_kernel(const float* __restrict__ src, uint32_t* __restrict__ dst, int n4)
{
    int i = blockIdx.x * 256 + threadIdx.x;
    if (i >= n4) return;
    float4 x = ((const float4*)src)[i];
    ((uint2*)dst)[i] = make_uint2(packh2(x.x, x.y), packh2(x.z, x.w));
}

// merged: all 4 weight matrices in one launch (blockIdx.y selects source)
__global__ __launch_bounds__(256)
void cvt_w4_kernel(const float* __restrict__ Wq, const float* __restrict__ Wk,
                   const float* __restrict__ Wv, const float* __restrict__ Wo,
                   uint32_t* __restrict__ dst, int n4w)
{
    const int z = blockIdx.y;
    const float* src = (z == 0) ? Wq : (z == 1) ? Wk : (z == 2) ? Wv : Wo;
    int i = blockIdx.x * 256 + threadIdx.x;
    if (i >= n4w) return;
    float4 x = ((const float4*)src)[i];
    ((uint2*)dst)[(size_t)z * n4w + i] = make_uint2(packh2(x.x, x.y), packh2(x.z, x.w));
}

// ===========================================================================
// FP16 tensor-core GEMM (m16n8k16), CTA 128x128, 4 warps (128 thr),
// warp tile 64x64. Double-buffered smem, one __syncthreads per k-iter.
// LDS.64 per warp per k16 step: 8 (A) + 8 (B) for 32 mma.
// ===========================================================================
#define GBM 128
#define GBN 128
#define GS  24          // padded smem row stride (u32) -> conflict-free LDS.64

__device__ __forceinline__ void mma_f16(float& c0, float& c1, float& c2, float& c3,
                                        uint32_t a0, uint32_t a1, uint32_t a2, uint32_t a3,
                                        uint32_t b0, uint32_t b1) {
    asm volatile("mma.sync.aligned.m16n8k16.row.col.f32.f16.f16.f32 "
                 "{%0,%1,%2,%3}, {%4,%5,%6,%7}, {%8,%9}, {%0,%1,%2,%3};"
                 : "+f"(c0), "+f"(c1), "+f"(c2), "+f"(c3)
                 : "r"(a0), "r"(a1), "r"(a2), "r"(a3), "r"(b0), "r"(b1));
}

__device__ __forceinline__ int permcol(int c) {
    int k8 = c >> 3;
    int cc = c & 7;
    return (k8 << 3) + ((cc & 3) << 1) + (cc >> 2);
}

struct GemmSmem {
    uint32_t As[2][GBM * GS];
    uint32_t Bs[2][GBN * GS];
};

template <bool HOUT>
__device__ __forceinline__
void gemm_core(const uint32_t* __restrict__ A,     // [M, EMB2] packed fp16
               const uint32_t* __restrict__ W,     // [EMBED, EMB2] packed fp16
               const float* __restrict__ bias,
               void* __restrict__ Cout,
               int M, float scale, GemmSmem& sh)
{
    const int tid   = threadIdx.x;
    const int warp  = tid >> 5;
    const int lane  = tid & 31;
    const int warpM = warp >> 1;     // 0..1
    const int warpN = warp & 1;      // 0..1
    const int g     = lane >> 2;
    const int t     = lane & 3;

    const int m0 = blockIdx.x * GBM;
    const int n0 = blockIdx.y * GBN;

    // staging map: 512 uint4 per matrix per tile / 128 threads = 4 each
    const int r4 = tid >> 2;                 // base row 0..31 (+32*i)
    const int c4 = (tid & 3) << 2;           // u32 col start (0,4,8,12)
    bool aOk[4];
#pragma unroll
    for (int i = 0; i < 4; i++) aOk[i] = (m0 + r4 + 32 * i) < M;

    int pc[4];
#pragma unroll
    for (int e = 0; e < 4; e++) pc[e] = permcol(c4 + e);

    float cacc[4][8][4];
#pragma unroll
    for (int i = 0; i < 4; i++)
#pragma unroll
        for (int j = 0; j < 8; j++)
#pragma unroll
            for (int e = 0; e < 4; e++) cacc[i][j][e] = 0.f;

    const uint4 z4 = make_uint4(0u, 0u, 0u, 0u);
    const uint32_t* pA = &A[(size_t)(m0 + r4) * EMB2 + c4];
    const uint32_t* pB = &W[(size_t)(n0 + r4) * EMB2 + c4];

    // prologue: k-tile 0 -> buffer 0
    {
#pragma unroll
        for (int i = 0; i < 4; i++) {
            uint4 a = aOk[i] ? *(const uint4*)(pA + (size_t)(32 * i) * EMB2) : z4;
            uint4 b = *(const uint4*)(pB + (size_t)(32 * i) * EMB2);
            const uint32_t va[4] = {a.x, a.y, a.z, a.w};
            const uint32_t vb[4] = {b.x, b.y, b.z, b.w};
#pragma unroll
            for (int e = 0; e < 4; e++) {
                sh.As[0][(r4 + 32 * i) * GS + pc[e]] = va[e];
                sh.Bs[0][(r4 + 32 * i) * GS + pc[e]] = vb[e];
            }
        }
    }
    __syncthreads();

    int p = 0;
    for (int kc = 0; kc < 32; kc++) {        // 32 k-tiles of 32 halves
        const bool more = (kc + 1 < 32);
        uint4 pa[4], pb[4];
        if (more) {
            const int kn = (kc + 1) * 16;    // u32 offset
#pragma unroll
            for (int i = 0; i < 4; i++) {
                pa[i] = aOk[i] ? *(const uint4*)(pA + (size_t)(32 * i) * EMB2 + kn) : z4;
                pb[i] = *(const uint4*)(pB + (size_t)(32 * i) * EMB2 + kn);
            }
        }

        // compute from buffer p: 2 k16 steps
        const uint32_t* Asp = sh.As[p];
        const uint32_t* Bsp = sh.Bs[p];
#pragma unroll
        for (int s = 0; s < 2; s++) {
            uint32_t af[4][4];
#pragma unroll
            for (int mt = 0; mt < 4; mt++) {
                const int row0 = warpM * 64 + mt * 16;
                uint2 lo = *(const uint2*)&Asp[(row0 + g)     * GS + s * 8 + 2 * t];
                uint2 hi = *(const uint2*)&Asp[(row0 + 8 + g) * GS + s * 8 + 2 * t];
                af[mt][0] = lo.x; af[mt][1] = hi.x; af[mt][2] = lo.y; af[mt][3] = hi.y;
            }
#pragma unroll
            for (int nt = 0; nt < 8; nt++) {
                const int nn0 = warpN * 64 + nt * 8;
                uint2 bb = *(const uint2*)&Bsp[(nn0 + g) * GS + s * 8 + 2 * t];
#pragma unroll
                for (int mt = 0; mt < 4; mt++) {
                    mma_f16(cacc[mt][nt][0], cacc[mt][nt][1], cacc[mt][nt][2], cacc[mt][nt][3],
                            af[mt][0], af[mt][1], af[mt][2], af[mt][3], bb.x, bb.y);
                }
            }
        }

        if (more) {
            uint32_t* Asn = sh.As[p ^ 1];
            uint32_t* Bsn = sh.Bs[p ^ 1];
#pragma unroll
            for (int i = 0; i < 4; i++) {
                const uint32_t va[4] = {pa[i].x, pa[i].y, pa[i].z, pa[i].w};
                const uint32_t vb[4] = {pb[i].x, pb[i].y, pb[i].z, pb[i].w};
#pragma unroll
                for (int e = 0; e < 4; e++) {
                    Asn[(r4 + 32 * i) * GS + pc[e]] = va[e];
                    Bsn[(r4 + 32 * i) * GS + pc[e]] = vb[e];
                }
            }
            __syncthreads();
            p ^= 1;
        }
    }

    // epilogue
#pragma unroll
    for (int nt = 0; nt < 8; nt++) {
        const int col = n0 + warpN * 64 + nt * 8 + 2 * t;   // even
        const float bn0 = bias[col];
        const float bn1 = bias[col + 1];
#pragma unroll
        for (int mt = 0; mt < 4; mt++) {
            const int row  = m0 + warpM * 64 + mt * 16 + g;
            const int row2 = row + 8;
            if (HOUT) {
                uint32_t* CH = (uint32_t*)Cout;
                if (row < M)
                    CH[(size_t)row * EMB2 + (col >> 1)] =
                        packh2((cacc[mt][nt][0] + bn0) * scale, (cacc[mt][nt][1] + bn1) * scale);
                if (row2 < M)
                    CH[(size_t)row2 * EMB2 + (col >> 1)] =
                        packh2((cacc[mt][nt][2] + bn0) * scale, (cacc[mt][nt][3] + bn1) * scale);
            } else {
                float* CF = (float*)Cout;
                if (row < M) {
                    float2 o = make_float2((cacc[mt][nt][0] + bn0) * scale,
                                           (cacc[mt][nt][1] + bn1) * scale);
                    *(float2*)&CF[(size_t)row * EMBED + col] = o;
                }
                if (row2 < M) {
                    float2 o = make_float2((cacc[mt][nt][2] + bn0) * scale,
                                           (cacc[mt][nt][3] + bn1) * scale);
                    *(float2*)&CF[(size_t)row2 * EMBED + col] = o;
                }
            }
        }
    }
}

// Fused QKV (fp16 output): blockIdx.z selects {Wq,Wk,Wv}.
__global__ __launch_bounds__(128, 2)
void gemm_qkv_kernel(const uint32_t* __restrict__ X,
                     const uint32_t* __restrict__ Wall,
                     const float* __restrict__ bq, const float* __restrict__ bk,
                     const float* __restrict__ bv,
                     uint32_t* __restrict__ q, uint32_t* __restrict__ k, uint32_t* __restrict__ v)
{
    __shared__ GemmSmem sh;
    const int z = blockIdx.z;
    const float* bias = (z == 0) ? bq : (z == 1) ? bk : bv;
    uint32_t*    C    = (z == 0) ? q  : (z == 1) ? k  : v;
    const float scale = (z == 0) ? ATTN_SCALE : 1.0f;
    gemm_core<true>(X, Wall + (size_t)z * EMBED * EMB2, bias, C, M_ROWS, scale, sh);
}

// Output projection (fp32 output)
__global__ __launch_bounds__(128, 2)
void gemm_single_kernel(const uint32_t* __restrict__ A, const uint32_t* __restrict__ W,
                        const float* __restrict__ bias, float* __restrict__ C,
                        int M, float scale)
{
    __shared__ GemmSmem sh;
    gemm_core<false>(A, W, bias, C, M, scale, sh);
}

// ===========================================================================
// Tensor-core attention (unchanged from R14): one CTA per (b,h), 8 warps,
// flash-style online softmax, m16n8k16 fp16 mma.
// ===========================================================================
#define SEQP  288
#define QROWS 272
#define QSTR  72
#define KSTR  72
#define VSTR  296
#define NCHUNK 9

__global__ __launch_bounds__(256, 1)
void attn_mma_kernel()
{
    extern __shared__ __half smh[];
    __half* Qh = smh;                       // QROWS * QSTR
    __half* Kh = Qh + QROWS * QSTR;         // SEQP * KSTR
    __half* Vt = Kh + SEQP * KSTR;          // 64 * VSTR

    const int tid  = threadIdx.x;
    const int w    = tid >> 5;
    const int lane = tid & 31;
    const int g    = lane >> 2;
    const int t    = lane & 3;
    const int b = blockIdx.x >> 4;
    const int h = blockIdx.x & 15;

    const size_t base2 = (size_t)b * SEQ * EMB2 + h * 32;

    for (int idx = tid; idx < QROWS * 32; idx += 256) {
        const int r = idx >> 5, c = idx & 31;
        const int rs = (r < SEQ) ? r : 0;
        *(uint32_t*)&Qh[r * QSTR + c * 2] = g_qh[base2 + (size_t)rs * EMB2 + c];
    }
    for (int idx = tid; idx < SEQP * 32; idx += 256) {
        const int r = idx >> 5, c = idx & 31;
        const int rs = (r < SEQ) ? r : 0;
        *(uint32_t*)&Kh[r * KSTR + c * 2] = g_kh[base2 + (size_t)rs * EMB2 + c];
    }
    for (int idx = tid; idx < SEQP * 32; idx += 256) {
        const int j = idx >> 5, c = idx & 31;
        const int js = (j < SEQ) ? j : 0;
        const uint32_t v2 = g_vh[base2 + (size_t)js * EMB2 + c];
        const __half2 hv = *reinterpret_cast<const __half2*>(&v2);
        Vt[(2 * c)     * VSTR + j] = __low2half(hv);
        Vt[(2 * c + 1) * VSTR + j] = __high2half(hv);
    }
    __syncthreads();

    for (int tile = w; tile < 17; tile += 8) {
        const int rb = tile * 16;

        uint32_t qf[4][4];
#pragma unroll
        for (int ks = 0; ks < 4; ks++) {
            const __half* qp  = &Qh[(rb + g) * QSTR + ks * 16 + 2 * t];
            const __half* qp8 = qp + 8 * QSTR;
            qf[ks][0] = *(const uint32_t*)qp;
            qf[ks][1] = *(const uint32_t*)qp8;
            qf[ks][2] = *(const uint32_t*)(qp + 8);
            qf[ks][3] = *(const uint32_t*)(qp8 + 8);
        }

        float of[8][4];
#pragma unroll
        for (int dn = 0; dn < 8; dn++)
#pragma unroll
            for (int e = 0; e < 4; e++) of[dn][e] = 0.f;
        float m0 = -1e30f, m1 = -1e30f, l0 = 0.f, l1 = 0.f;

        for (int cb = 0; cb < NCHUNK; cb++) {
            const int kb = cb * 32;

            float sf[4][4];
#pragma unroll
            for (int nt = 0; nt < 4; nt++)
#pragma unroll
                for (int e = 0; e < 4; e++) sf[nt][e] = 0.f;

#pragma unroll
            for (int nt = 0; nt < 4; nt++) {
                const __half* kp0 = &Kh[(kb + nt * 8 + g) * KSTR + 2 * t];
#pragma unroll
                for (int ks = 0; ks < 4; ks++) {
                    const uint32_t b0 = *(const uint32_t*)(kp0 + ks * 16);
                    const uint32_t b1 = *(const uint32_t*)(kp0 + ks * 16 + 8);
                    mma_f16(sf[nt][0], sf[nt][1], sf[nt][2], sf[nt][3],
                            qf[ks][0], qf[ks][1], qf[ks][2], qf[ks][3], b0, b1);
                }
            }

            if (cb == NCHUNK - 1) {
#pragma unroll
                for (int nt = 0; nt < 4; nt++) {
                    const int c0 = 256 + nt * 8 + 2 * t;
                    if (c0     >= SEQ) { sf[nt][0] = -1e30f; sf[nt][2] = -1e30f; }
                    if (c0 + 1 >= SEQ) { sf[nt][1] = -1e30f; sf[nt][3] = -1e30f; }
                }
            }

            float cm0 = sf[0][0], cm1 = sf[0][2];
#pragma unroll
            for (int nt = 0; nt < 4; nt++) {
                cm0 = fmaxf(cm0, fmaxf(sf[nt][0], sf[nt][1]));
                cm1 = fmaxf(cm1, fmaxf(sf[nt][2], sf[nt][3]));
            }
            cm0 = fmaxf(cm0, __shfl_xor_sync(0xffffffffu, cm0, 1));
            cm0 = fmaxf(cm0, __shfl_xor_sync(0xffffffffu, cm0, 2));
            cm1 = fmaxf(cm1, __shfl_xor_sync(0xffffffffu, cm1, 1));
            cm1 = fmaxf(cm1, __shfl_xor_sync(0xffffffffu, cm1, 2));

            const float mn0 = fmaxf(m0, cm0);
            const float mn1 = fmaxf(m1, cm1);
            const float a0 = __expf(m0 - mn0);
            const float a1 = __expf(m1 - mn1);
            m0 = mn0; m1 = mn1;

            float ps0 = 0.f, ps1 = 0.f;
#pragma unroll
            for (int nt = 0; nt < 4; nt++) {
                sf[nt][0] = __expf(sf[nt][0] - m0); ps0 += sf[nt][0];
                sf[nt][1] = __expf(sf[nt][1] - m0); ps0 += sf[nt][1];
                sf[nt][2] = __expf(sf[nt][2] - m1); ps1 += sf[nt][2];
                sf[nt][3] = __expf(sf[nt][3] - m1); ps1 += sf[nt][3];
            }
            l0 = l0 * a0 + ps0;
            l1 = l1 * a1 + ps1;

#pragma unroll
            for (int dn = 0; dn < 8; dn++) {
                of[dn][0] *= a0; of[dn][1] *= a0;
                of[dn][2] *= a1; of[dn][3] *= a1;
            }

            uint32_t pf[2][4];
#pragma unroll
            for (int ks = 0; ks < 2; ks++) {
                pf[ks][0] = packh2(sf[2 * ks][0],     sf[2 * ks][1]);
                pf[ks][1] = packh2(sf[2 * ks][2],     sf[2 * ks][3]);
                pf[ks][2] = packh2(sf[2 * ks + 1][0], sf[2 * ks + 1][1]);
                pf[ks][3] = packh2(sf[2 * ks + 1][2], sf[2 * ks + 1][3]);
            }

#pragma unroll
            for (int dn = 0; dn < 8; dn++) {
                const __half* vp0 = &Vt[(dn * 8 + g) * VSTR + kb + 2 * t];
#pragma unroll
                for (int ks = 0; ks < 2; ks++) {
                    const uint32_t b0 = *(const uint32_t*)(vp0 + ks * 16);
                    const uint32_t b1 = *(const uint32_t*)(vp0 + ks * 16 + 8);
                    mma_f16(of[dn][0], of[dn][1], of[dn][2], of[dn][3],
                            pf[ks][0], pf[ks][1], pf[ks][2], pf[ks][3], b0, b1);
                }
            }
        }

        l0 += __shfl_xor_sync(0xffffffffu, l0, 1);
        l0 += __shfl_xor_sync(0xffffffffu, l0, 2);
        l1 += __shfl_xor_sync(0xffffffffu, l1, 1);
        l1 += __shfl_xor_sync(0xffffffffu, l1, 2);
        const float inv0 = 1.f / l0;
        const float inv1 = 1.f / l1;

        const int r0 = rb + g;
        const int r1 = rb + g + 8;
#pragma unroll
        for (int dn = 0; dn < 8; dn++) {
            const size_t cidx = (size_t)h * 32 + dn * 4 + t;
            if (r0 < SEQ)
                g_ch[((size_t)b * SEQ + r0) * EMB2 + cidx] =
                    packh2(of[dn][0] * inv0, of[dn][1] * inv0);
            if (r1 < SEQ)
                g_ch[((size_t)b * SEQ + r1) * EMB2 + cidx] =
                    packh2(of[dn][2] * inv1, of[dn][3] * inv1);
        }
    }
}

// ===========================================================================
extern "C" void kernel_launch(void* const* d_in, const int* in_sizes, int n_in,
                              void* d_out, int out_size)
{
    const float* X  = (const float*)d_in[0];
    const float* Wq = (const float*)d_in[1];
    const float* bq = (const float*)d_in[2];
    const float* Wk = (const float*)d_in[3];
    const float* bk = (const float*)d_in[4];
    const float* Wv = (const float*)d_in[5];
    const float* bv = (const float*)d_in[6];
    const float* Wo = (const float*)d_in[7];
    const float* bo = (const float*)d_in[8];
    float* out = (float*)d_out;

    uint32_t *qh, *kh, *vh, *ch, *xh, *wh;
    cudaGetSymbolAddress((void**)&qh, g_qh);
    cudaGetSymbolAddress((void**)&kh, g_kh);
    cudaGetSymbolAddress((void**)&vh, g_vh);
    cudaGetSymbolAddress((void**)&ch, g_ch);
    cudaGetSymbolAddress((void**)&xh, g_xh);
    cudaGetSymbolAddress((void**)&wh, g_wh);

    const int WPLANE = EMBED * EMB2;
    const int n4x = M_ROWS * EMBED / 4;
    const int n4w = EMBED * EMBED / 4;

    // 1. pack X (one launch) and all four weight matrices (one merged launch)
    cvt_f16_kernel<<<(n4x + 255) / 256, 256>>>(X, xh, n4x);
    cvt_w4_kernel<<<dim3((n4w + 255) / 256, 4), 256>>>(Wq, Wk, Wv, Wo, wh, n4w);

    // 2. fused Q/K/V projections -> packed fp16 (Q carries attention scale)
    const dim3 gBlk(128);
    const dim3 qkvGrid((M_ROWS + GBM - 1) / GBM, EMBED / GBN, 3);
    gemm_qkv_kernel<<<qkvGrid, gBlk>>>(xh, wh, bq, bk, bv, qh, kh, vh);

    // 3. tensor-core attention -> ctx packed fp16
    const int smemBytes = (QROWS * QSTR + SEQP * KSTR + 64 * VSTR) * (int)sizeof(__half);
    cudaFuncSetAttribute(attn_mma_kernel, cudaFuncAttributeMaxDynamicSharedMemorySize, smemBytes);
    attn_mma_kernel<<<BATCH * HEADS, 256, smemBytes>>>();

    // 4. output projection (fp32 out)
    const dim3 oGrid((M_ROWS + GBM - 1) / GBM, EMBED / GBN);
    gemm_single_kernel<<<oGrid, gBlk>>>(ch, wh + 3 * WPLANE, bo, out, M_ROWS, 1.0f);
}

// round 17
// speedup vs baseline: 7.0570x; 1.0910x over previous
#include <cstdint>
#include <cstdio>
#include <cuda_runtime.h>
#include <cuda_fp16.h>
#include <math_constants.h>

// Problem constants
#define BATCH   32
#define SEQ     257
#define EMBED   1024
#define EMB2    512                  // EMBED/2 in u32 (packed half2)
#define HEADS   16
#define HEAD_D  64
#define M_ROWS  (BATCH * SEQ)        // 8224
#define ATTN_SCALE 0.125f

// Scratch (device globals; no allocation allowed)
__device__ uint32_t g_qh[M_ROWS * EMB2];         // Q packed fp16 (scaled)
__device__ uint32_t g_kh[M_ROWS * EMB2];         // K packed fp16
__device__ uint32_t g_vh[M_ROWS * EMB2];         // V packed fp16
__device__ uint32_t g_ch[M_ROWS * EMB2];         // ctx packed fp16
__device__ uint32_t g_xh[M_ROWS * EMB2];         // X packed fp16
__device__ uint32_t g_wh[4 * EMBED * EMB2];      // Wq, Wk, Wv, Wo packed fp16

__device__ __forceinline__ uint32_t packh2(float a, float b) {
    __half2 hh = __floats2half2_rn(a, b);
    return *reinterpret_cast<uint32_t*>(&hh);
}

// ===========================================================================
// fp32 -> packed fp16 conversion
// ===========================================================================
__global__ __launch_bounds__(256)
void cvt_f16_kernel(const float* __restrict__ src, uint32_t* __restrict__ dst, int n4)
{
    int i = blockIdx.x * 256 + threadIdx.x;
    if (i >= n4) return;
    float4 x = ((const float4*)src)[i];
    ((uint2*)dst)[i] = make_uint2(packh2(x.x, x.y), packh2(x.z, x.w));
}

// merged: all 4 weight matrices in one launch (blockIdx.y selects source)
__global__ __launch_bounds__(256)
void cvt_w4_kernel(const float* __restrict__ Wq, const float* __restrict__ Wk,
                   const float* __restrict__ Wv, const float* __restrict__ Wo,
                   uint32_t* __restrict__ dst, int n4w)
{
    const int z = blockIdx.y;
    const float* src = (z == 0) ? Wq : (z == 1) ? Wk : (z == 2) ? Wv : Wo;
    int i = blockIdx.x * 256 + threadIdx.x;
    if (i >= n4w) return;
    float4 x = ((const float4*)src)[i];
    ((uint2*)dst)[(size_t)z * n4w + i] = make_uint2(packh2(x.x, x.y), packh2(x.z, x.w));
}

// ===========================================================================
// FP16 tensor-core GEMM (m16n8k16), CTA 128x128, 4 warps (128 thr),
// warp tile 64x64. Double-buffered smem, one __syncthreads per k-iter.
// (unchanged from R16)
// ===========================================================================
#define GBM 128
#define GBN 128
#define GS  24          // padded smem row stride (u32) -> conflict-free LDS.64

__device__ __forceinline__ void mma_f16(float& c0, float& c1, float& c2, float& c3,
                                        uint32_t a0, uint32_t a1, uint32_t a2, uint32_t a3,
                                        uint32_t b0, uint32_t b1) {
    asm volatile("mma.sync.aligned.m16n8k16.row.col.f32.f16.f16.f32 "
                 "{%0,%1,%2,%3}, {%4,%5,%6,%7}, {%8,%9}, {%0,%1,%2,%3};"
                 : "+f"(c0), "+f"(c1), "+f"(c2), "+f"(c3)
                 : "r"(a0), "r"(a1), "r"(a2), "r"(a3), "r"(b0), "r"(b1));
}

__device__ __forceinline__ int permcol(int c) {
    int k8 = c >> 3;
    int cc = c & 7;
    return (k8 << 3) + ((cc & 3) << 1) + (cc >> 2);
}

struct GemmSmem {
    uint32_t As[2][GBM * GS];
    uint32_t Bs[2][GBN * GS];
};

template <bool HOUT>
__device__ __forceinline__
void gemm_core(const uint32_t* __restrict__ A,     // [M, EMB2] packed fp16
               const uint32_t* __restrict__ W,     // [EMBED, EMB2] packed fp16
               const float* __restrict__ bias,
               void* __restrict__ Cout,
               int M, float scale, GemmSmem& sh)
{
    const int tid   = threadIdx.x;
    const int warp  = tid >> 5;
    const int lane  = tid & 31;
    const int warpM = warp >> 1;     // 0..1
    const int warpN = warp & 1;      // 0..1
    const int g     = lane >> 2;
    const int t     = lane & 3;

    const int m0 = blockIdx.x * GBM;
    const int n0 = blockIdx.y * GBN;

    const int r4 = tid >> 2;                 // base row 0..31 (+32*i)
    const int c4 = (tid & 3) << 2;           // u32 col start (0,4,8,12)
    bool aOk[4];
#pragma unroll
    for (int i = 0; i < 4; i++) aOk[i] = (m0 + r4 + 32 * i) < M;

    int pc[4];
#pragma unroll
    for (int e = 0; e < 4; e++) pc[e] = permcol(c4 + e);

    float cacc[4][8][4];
#pragma unroll
    for (int i = 0; i < 4; i++)
#pragma unroll
        for (int j = 0; j < 8; j++)
#pragma unroll
            for (int e = 0; e < 4; e++) cacc[i][j][e] = 0.f;

    const uint4 z4 = make_uint4(0u, 0u, 0u, 0u);
    const uint32_t* pA = &A[(size_t)(m0 + r4) * EMB2 + c4];
    const uint32_t* pB = &W[(size_t)(n0 + r4) * EMB2 + c4];

    {
#pragma unroll
        for (int i = 0; i < 4; i++) {
            uint4 a = aOk[i] ? *(const uint4*)(pA + (size_t)(32 * i) * EMB2) : z4;
            uint4 b = *(const uint4*)(pB + (size_t)(32 * i) * EMB2);
            const uint32_t va[4] = {a.x, a.y, a.z, a.w};
            const uint32_t vb[4] = {b.x, b.y, b.z, b.w};
#pragma unroll
            for (int e = 0; e < 4; e++) {
                sh.As[0][(r4 + 32 * i) * GS + pc[e]] = va[e];
                sh.Bs[0][(r4 + 32 * i) * GS + pc[e]] = vb[e];
            }
        }
    }
    __syncthreads();

    int p = 0;
    for (int kc = 0; kc < 32; kc++) {
        const bool more = (kc + 1 < 32);
        uint4 pa[4], pb[4];
        if (more) {
            const int kn = (kc + 1) * 16;
#pragma unroll
            for (int i = 0; i < 4; i++) {
                pa[i] = aOk[i] ? *(const uint4*)(pA + (size_t)(32 * i) * EMB2 + kn) : z4;
                pb[i] = *(const uint4*)(pB + (size_t)(32 * i) * EMB2 + kn);
            }
        }

        const uint32_t* Asp = sh.As[p];
        const uint32_t* Bsp = sh.Bs[p];
#pragma unroll
        for (int s = 0; s < 2; s++) {
            uint32_t af[4][4];
#pragma unroll
            for (int mt = 0; mt < 4; mt++) {
                const int row0 = warpM * 64 + mt * 16;
                uint2 lo = *(const uint2*)&Asp[(row0 + g)     * GS + s * 8 + 2 * t];
                uint2 hi = *(const uint2*)&Asp[(row0 + 8 + g) * GS + s * 8 + 2 * t];
                af[mt][0] = lo.x; af[mt][1] = hi.x; af[mt][2] = lo.y; af[mt][3] = hi.y;
            }
#pragma unroll
            for (int nt = 0; nt < 8; nt++) {
                const int nn0 = warpN * 64 + nt * 8;
                uint2 bb = *(const uint2*)&Bsp[(nn0 + g) * GS + s * 8 + 2 * t];
#pragma unroll
                for (int mt = 0; mt < 4; mt++) {
                    mma_f16(cacc[mt][nt][0], cacc[mt][nt][1], cacc[mt][nt][2], cacc[mt][nt][3],
                            af[mt][0], af[mt][1], af[mt][2], af[mt][3], bb.x, bb.y);
                }
            }
        }

        if (more) {
            uint32_t* Asn = sh.As[p ^ 1];
            uint32_t* Bsn = sh.Bs[p ^ 1];
#pragma unroll
            for (int i = 0; i < 4; i++) {
                const uint32_t va[4] = {pa[i].x, pa[i].y, pa[i].z, pa[i].w};
                const uint32_t vb[4] = {pb[i].x, pb[i].y, pb[i].z, pb[i].w};
#pragma unroll
                for (int e = 0; e < 4; e++) {
                    Asn[(r4 + 32 * i) * GS + pc[e]] = va[e];
                    Bsn[(r4 + 32 * i) * GS + pc[e]] = vb[e];
                }
            }
            __syncthreads();
            p ^= 1;
        }
    }

    // epilogue
#pragma unroll
    for (int nt = 0; nt < 8; nt++) {
        const int col = n0 + warpN * 64 + nt * 8 + 2 * t;   // even
        const float bn0 = bias[col];
        const float bn1 = bias[col + 1];
#pragma unroll
        for (int mt = 0; mt < 4; mt++) {
            const int row  = m0 + warpM * 64 + mt * 16 + g;
            const int row2 = row + 8;
            if (HOUT) {
                uint32_t* CH = (uint32_t*)Cout;
                if (row < M)
                    CH[(size_t)row * EMB2 + (col >> 1)] =
                        packh2((cacc[mt][nt][0] + bn0) * scale, (cacc[mt][nt][1] + bn1) * scale);
                if (row2 < M)
                    CH[(size_t)row2 * EMB2 + (col >> 1)] =
                        packh2((cacc[mt][nt][2] + bn0) * scale, (cacc[mt][nt][3] + bn1) * scale);
            } else {
                float* CF = (float*)Cout;
                if (row < M) {
                    float2 o = make_float2((cacc[mt][nt][0] + bn0) * scale,
                                           (cacc[mt][nt][1] + bn1) * scale);
                    *(float2*)&CF[(size_t)row * EMBED + col] = o;
                }
                if (row2 < M) {
                    float2 o = make_float2((cacc[mt][nt][2] + bn0) * scale,
                                           (cacc[mt][nt][3] + bn1) * scale);
                    *(float2*)&CF[(size_t)row2 * EMBED + col] = o;
                }
            }
        }
    }
}

// Fused QKV (fp16 output): blockIdx.z selects {Wq,Wk,Wv}.
__global__ __launch_bounds__(128, 2)
void gemm_qkv_kernel(const uint32_t* __restrict__ X,
                     const uint32_t* __restrict__ Wall,
                     const float* __restrict__ bq, const float* __restrict__ bk,
                     const float* __restrict__ bv,
                     uint32_t* __restrict__ q, uint32_t* __restrict__ k, uint32_t* __restrict__ v)
{
    __shared__ GemmSmem sh;
    const int z = blockIdx.z;
    const float* bias = (z == 0) ? bq : (z == 1) ? bk : bv;
    uint32_t*    C    = (z == 0) ? q  : (z == 1) ? k  : v;
    const float scale = (z == 0) ? ATTN_SCALE : 1.0f;
    gemm_core<true>(X, Wall + (size_t)z * EMBED * EMB2, bias, C, M_ROWS, scale, sh);
}

// Output projection (fp32 output)
__global__ __launch_bounds__(128, 2)
void gemm_single_kernel(const uint32_t* __restrict__ A, const uint32_t* __restrict__ W,
                        const float* __restrict__ bias, float* __restrict__ C,
                        int M, float scale)
{
    __shared__ GemmSmem sh;
    gemm_core<false>(A, W, bias, C, M, scale, sh);
}

// ===========================================================================
// Tensor-core attention: one CTA per (b,h), 8 warps, flash-style online
// softmax, m16n8k16 fp16 mma.
// R17 change: Q fragments loaded DIRECTLY from gmem (L2-hot) — Q smem stage
// removed. smem = K + Vt only (77.5KB) -> 2 CTAs/SM, 16 warps/SM.
// ===========================================================================
#define SEQP  288
#define KSTR  72
#define VSTR  296
#define NCHUNK 9

__global__ __launch_bounds__(256, 2)
void attn_mma_kernel()
{
    extern __shared__ __half smh[];
    __half* Kh = smh;                       // SEQP * KSTR
    __half* Vt = Kh + SEQP * KSTR;          // 64 * VSTR

    const int tid  = threadIdx.x;
    const int w    = tid >> 5;
    const int lane = tid & 31;
    const int g    = lane >> 2;
    const int t    = lane & 3;
    const int b = blockIdx.x >> 4;
    const int h = blockIdx.x & 15;

    const size_t base2 = (size_t)b * SEQ * EMB2 + h * 32;   // u32 offset of this head

    // stage K
    for (int idx = tid; idx < SEQP * 32; idx += 256) {
        const int r = idx >> 5, c = idx & 31;
        const int rs = (r < SEQ) ? r : 0;
        *(uint32_t*)&Kh[r * KSTR + c * 2] = g_kh[base2 + (size_t)rs * EMB2 + c];
    }
    // stage V transposed: Vt[dim][key]
    for (int idx = tid; idx < SEQP * 32; idx += 256) {
        const int j = idx >> 5, c = idx & 31;
        const int js = (j < SEQ) ? j : 0;
        const uint32_t v2 = g_vh[base2 + (size_t)js * EMB2 + c];
        const __half2 hv = *reinterpret_cast<const __half2*>(&v2);
        Vt[(2 * c)     * VSTR + j] = __low2half(hv);
        Vt[(2 * c + 1) * VSTR + j] = __high2half(hv);
    }
    __syncthreads();

    for (int tile = w; tile < 17; tile += 8) {
        const int rb = tile * 16;

        // Q fragments straight from gmem (each row used once; no smem reuse)
        const int r0g = rb + g;
        const int r8g = rb + g + 8;
        const uint32_t* qrow0 = g_qh + base2 + (size_t)((r0g < SEQ) ? r0g : 0) * EMB2;
        const uint32_t* qrow8 = g_qh + base2 + (size_t)((r8g < SEQ) ? r8g : 0) * EMB2;
        uint32_t qf[4][4];
#pragma unroll
        for (int ks = 0; ks < 4; ks++) {
            qf[ks][0] = qrow0[ks * 8 + t];
            qf[ks][1] = qrow8[ks * 8 + t];
            qf[ks][2] = qrow0[ks * 8 + t + 4];
            qf[ks][3] = qrow8[ks * 8 + t + 4];
        }

        float of[8][4];
#pragma unroll
        for (int dn = 0; dn < 8; dn++)
#pragma unroll
            for (int e = 0; e < 4; e++) of[dn][e] = 0.f;
        float m0 = -1e30f, m1 = -1e30f, l0 = 0.f, l1 = 0.f;

        for (int cb = 0; cb < NCHUNK; cb++) {
            const int kb = cb * 32;

            float sf[4][4];
#pragma unroll
            for (int nt = 0; nt < 4; nt++)
#pragma unroll
                for (int e = 0; e < 4; e++) sf[nt][e] = 0.f;

#pragma unroll
            for (int nt = 0; nt < 4; nt++) {
                const __half* kp0 = &Kh[(kb + nt * 8 + g) * KSTR + 2 * t];
#pragma unroll
                for (int ks = 0; ks < 4; ks++) {
                    const uint32_t b0 = *(const uint32_t*)(kp0 + ks * 16);
                    const uint32_t b1 = *(const uint32_t*)(kp0 + ks * 16 + 8);
                    mma_f16(sf[nt][0], sf[nt][1], sf[nt][2], sf[nt][3],
                            qf[ks][0], qf[ks][1], qf[ks][2], qf[ks][3], b0, b1);
                }
            }

            if (cb == NCHUNK - 1) {
#pragma unroll
                for (int nt = 0; nt < 4; nt++) {
                    const int c0 = 256 + nt * 8 + 2 * t;
                    if (c0     >= SEQ) { sf[nt][0] = -1e30f; sf[nt][2] = -1e30f; }
                    if (c0 + 1 >= SEQ) { sf[nt][1] = -1e30f; sf[nt][3] = -1e30f; }
                }
            }

            float cm0 = sf[0][0], cm1 = sf[0][2];
#pragma unroll
            for (int nt = 0; nt < 4; nt++) {
                cm0 = fmaxf(cm0, fmaxf(sf[nt][0], sf[nt][1]));
                cm1 = fmaxf(cm1, fmaxf(sf[nt][2], sf[nt][3]));
            }
            cm0 = fmaxf(cm0, __shfl_xor_sync(0xffffffffu, cm0, 1));
            cm0 = fmaxf(cm0, __shfl_xor_sync(0xffffffffu, cm0, 2));
            cm1 = fmaxf(cm1, __shfl_xor_sync(0xffffffffu, cm1, 1));
            cm1 = fmaxf(cm1, __shfl_xor_sync(0xffffffffu, cm1, 2));

            const float mn0 = fmaxf(m0, cm0);
            const float mn1 = fmaxf(m1, cm1);
            const float a0 = __expf(m0 - mn0);
            const float a1 = __expf(m1 - mn1);
            m0 = mn0; m1 = mn1;

            float ps0 = 0.f, ps1 = 0.f;
#pragma unroll
            for (int nt = 0; nt < 4; nt++) {
                sf[nt][0] = __expf(sf[nt][0] - m0); ps0 += sf[nt][0];
                sf[nt][1] = __expf(sf[nt][1] - m0); ps0 += sf[nt][1];
                sf[nt][2] = __expf(sf[nt][2] - m1); ps1 += sf[nt][2];
                sf[nt][3] = __expf(sf[nt][3] - m1); ps1 += sf[nt][3];
            }
            l0 = l0 * a0 + ps0;
            l1 = l1 * a1 + ps1;

#pragma unroll
            for (int dn = 0; dn < 8; dn++) {
                of[dn][0] *= a0; of[dn][1] *= a0;
                of[dn][2] *= a1; of[dn][3] *= a1;
            }

            uint32_t pf[2][4];
#pragma unroll
            for (int ks = 0; ks < 2; ks++) {
                pf[ks][0] = packh2(sf[2 * ks][0],     sf[2 * ks][1]);
                pf[ks][1] = packh2(sf[2 * ks][2],     sf[2 * ks][3]);
                pf[ks][2] = packh2(sf[2 * ks + 1][0], sf[2 * ks + 1][1]);
                pf[ks][3] = packh2(sf[2 * ks + 1][2], sf[2 * ks + 1][3]);
            }

#pragma unroll
            for (int dn = 0; dn < 8; dn++) {
                const __half* vp0 = &Vt[(dn * 8 + g) * VSTR + kb + 2 * t];
#pragma unroll
                for (int ks = 0; ks < 2; ks++) {
                    const uint32_t b0 = *(const uint32_t*)(vp0 + ks * 16);
                    const uint32_t b1 = *(const uint32_t*)(vp0 + ks * 16 + 8);
                    mma_f16(of[dn][0], of[dn][1], of[dn][2], of[dn][3],
                            pf[ks][0], pf[ks][1], pf[ks][2], pf[ks][3], b0, b1);
                }
            }
        }

        l0 += __shfl_xor_sync(0xffffffffu, l0, 1);
        l0 += __shfl_xor_sync(0xffffffffu, l0, 2);
        l1 += __shfl_xor_sync(0xffffffffu, l1, 1);
        l1 += __shfl_xor_sync(0xffffffffu, l1, 2);
        const float inv0 = 1.f / l0;
        const float inv1 = 1.f / l1;

        const int r0 = rb + g;
        const int r1 = rb + g + 8;
#pragma unroll
        for (int dn = 0; dn < 8; dn++) {
            const size_t cidx = (size_t)h * 32 + dn * 4 + t;
            if (r0 < SEQ)
                g_ch[((size_t)b * SEQ + r0) * EMB2 + cidx] =
                    packh2(of[dn][0] * inv0, of[dn][1] * inv0);
            if (r1 < SEQ)
                g_ch[((size_t)b * SEQ + r1) * EMB2 + cidx] =
                    packh2(of[dn][2] * inv1, of[dn][3] * inv1);
        }
    }
}

// ===========================================================================
extern "C" void kernel_launch(void* const* d_in, const int* in_sizes, int n_in,
                              void* d_out, int out_size)
{
    const float* X  = (const float*)d_in[0];
    const float* Wq = (const float*)d_in[1];
    const float* bq = (const float*)d_in[2];
    const float* Wk = (const float*)d_in[3];
    const float* bk = (const float*)d_in[4];
    const float* Wv = (const float*)d_in[5];
    const float* bv = (const float*)d_in[6];
    const float* Wo = (const float*)d_in[7];
    const float* bo = (const float*)d_in[8];
    float* out = (float*)d_out;

    uint32_t *qh, *kh, *vh, *ch, *xh, *wh;
    cudaGetSymbolAddress((void**)&qh, g_qh);
    cudaGetSymbolAddress((void**)&kh, g_kh);
    cudaGetSymbolAddress((void**)&vh, g_vh);
    cudaGetSymbolAddress((void**)&ch, g_ch);
    cudaGetSymbolAddress((void**)&xh, g_xh);
    cudaGetSymbolAddress((void**)&wh, g_wh);

    const int WPLANE = EMBED * EMB2;
    const int n4x = M_ROWS * EMBED / 4;
    const int n4w = EMBED * EMBED / 4;

    // 1. pack X (one launch) and all four weight matrices (one merged launch)
    cvt_f16_kernel<<<(n4x + 255) / 256, 256>>>(X, xh, n4x);
    cvt_w4_kernel<<<dim3((n4w + 255) / 256, 4), 256>>>(Wq, Wk, Wv, Wo, wh, n4w);

    // 2. fused Q/K/V projections -> packed fp16 (Q carries attention scale)
    const dim3 gBlk(128);
    const dim3 qkvGrid((M_ROWS + GBM - 1) / GBM, EMBED / GBN, 3);
    gemm_qkv_kernel<<<qkvGrid, gBlk>>>(xh, wh, bq, bk, bv, qh, kh, vh);

    // 3. tensor-core attention -> ctx packed fp16 (K + Vt smem only)
    const int smemBytes = (SEQP * KSTR + 64 * VSTR) * (int)sizeof(__half);
    cudaFuncSetAttribute(attn_mma_kernel, cudaFuncAttributeMaxDynamicSharedMemorySize, smemBytes);
    attn_mma_kernel<<<BATCH * HEADS, 256, smemBytes>>>();

    // 4. output projection (fp32 out)
    const dim3 oGrid((M_ROWS + GBM - 1) / GBM, EMBED / GBN);
    gemm_single_kernel<<<oGrid, gBlk>>>(ch, wh + 3 * WPLANE, bo, out, M_ROWS, 1.0f);
}